// round 2
// baseline (speedup 1.0000x reference)
#include <cuda_runtime.h>
#include <math.h>
#include <stdint.h>

// ---------------- problem constants ----------------
#define BATCH   2
#define SLEN    2048
#define DMODEL  1024
#define NHEAD   16
#define DHEAD   64
#define NROWS   (BATCH * SLEN)          // 4096
#define QKVD    (3 * DMODEL)            // 3072
#define NQT     (SLEN / 64)             // 32 query tiles per (b,h)
#define ATT_SCALE 0.125f                // 1/sqrt(64)

// ---------------- scratch (device globals; no allocations allowed) --------
__device__ float g_xn_l[NROWS * DMODEL];
__device__ float g_xn_g[NROWS * DMODEL];
__device__ float g_qkv_l[(size_t)NROWS * QKVD];
__device__ float g_qkv_g[(size_t)NROWS * QKVD];
__device__ float g_ao_l[NROWS * DMODEL];
__device__ float g_ao_g[NROWS * DMODEL];

// ============================================================
// Kernel 1: fused dual LayerNorm (one mean/var, two (gamma,beta) pairs)
// grid = NROWS blocks, 256 threads; each thread handles 4 columns.
// ============================================================
__global__ __launch_bounds__(256) void ln_dual_kernel(
    const float* __restrict__ x,
    const float* __restrict__ gl, const float* __restrict__ bl,
    const float* __restrict__ gg, const float* __restrict__ bg,
    float* __restrict__ xl, float* __restrict__ xg)
{
    int row = blockIdx.x;
    const float* xr = x + (size_t)row * DMODEL;
    int t = threadIdx.x;

    float v[4];
    float s = 0.f, s2 = 0.f;
#pragma unroll
    for (int i = 0; i < 4; i++) {
        float a = xr[t + i * 256];
        v[i] = a; s += a; s2 += a * a;
    }
    // warp reduce
#pragma unroll
    for (int o = 16; o > 0; o >>= 1) {
        s  += __shfl_xor_sync(0xffffffffu, s,  o);
        s2 += __shfl_xor_sync(0xffffffffu, s2, o);
    }
    __shared__ float red0[8], red1[8], stat[2];
    int warp = t >> 5, lane = t & 31;
    if (lane == 0) { red0[warp] = s; red1[warp] = s2; }
    __syncthreads();
    if (t < 32) {
        float a = (t < 8) ? red0[t] : 0.f;
        float b = (t < 8) ? red1[t] : 0.f;
#pragma unroll
        for (int o = 4; o > 0; o >>= 1) {
            a += __shfl_xor_sync(0xffffffffu, a, o);
            b += __shfl_xor_sync(0xffffffffu, b, o);
        }
        if (t == 0) {
            float mean = a * (1.f / DMODEL);
            float var  = b * (1.f / DMODEL) - mean * mean;
            stat[0] = mean;
            stat[1] = rsqrtf(var + 1e-5f);
        }
    }
    __syncthreads();
    float mean = stat[0], rstd = stat[1];
    float* xlr = xl + (size_t)row * DMODEL;
    float* xgr = xg + (size_t)row * DMODEL;
#pragma unroll
    for (int i = 0; i < 4; i++) {
        int c = t + i * 256;
        float n = (v[i] - mean) * rstd;
        xlr[c] = n * gl[c] + bl[c];
        xgr[c] = n * gg[c] + bg[c];
    }
}

// ============================================================
// Kernel 2: SGEMM  C[M,N] = A[M,K] * W[N,K]^T + bias[N] (+C if accum)
// Both operands K-contiguous (TN).  128x128x8 tile, 256 threads, 8x8 microtile.
// M%128==0, N%128==0, K%8==0 guaranteed by problem sizes.
// ============================================================
#define BM 128
#define BN 128
#define BK 8
__global__ __launch_bounds__(256, 2) void sgemm_tn(
    const float* __restrict__ A, const float* __restrict__ W,
    const float* __restrict__ bias, float* __restrict__ C,
    int M, int N, int K, int accum)
{
    __shared__ float As[BK][BM];
    __shared__ float Ws[BK][BN];

    int tid = threadIdx.x;
    int m0 = blockIdx.y * BM;
    int n0 = blockIdx.x * BN;

    int lr = tid >> 1;            // 0..127 : row within tile
    int lk = (tid & 1) * 4;       // 0 or 4 : k offset (float4)
    const float* Ap = A + (size_t)(m0 + lr) * K + lk;
    const float* Wp = W + (size_t)(n0 + lr) * K + lk;

    int ty = tid >> 4;            // 0..15
    int tx = tid & 15;            // 0..15

    float acc[8][8];
#pragma unroll
    for (int i = 0; i < 8; i++)
#pragma unroll
        for (int j = 0; j < 8; j++) acc[i][j] = 0.f;

    for (int kt = 0; kt < K; kt += BK) {
        float4 a4 = *(const float4*)(Ap + kt);
        float4 w4 = *(const float4*)(Wp + kt);
        As[lk + 0][lr] = a4.x; As[lk + 1][lr] = a4.y;
        As[lk + 2][lr] = a4.z; As[lk + 3][lr] = a4.w;
        Ws[lk + 0][lr] = w4.x; Ws[lk + 1][lr] = w4.y;
        Ws[lk + 2][lr] = w4.z; Ws[lk + 3][lr] = w4.w;
        __syncthreads();

#pragma unroll
        for (int k = 0; k < BK; k++) {
            float a[8], b[8];
#pragma unroll
            for (int i = 0; i < 8; i++) a[i] = As[k][ty * 8 + i];
#pragma unroll
            for (int j = 0; j < 8; j++) b[j] = Ws[k][tx * 8 + j];
#pragma unroll
            for (int i = 0; i < 8; i++)
#pragma unroll
                for (int j = 0; j < 8; j++)
                    acc[i][j] += a[i] * b[j];
        }
        __syncthreads();
    }

    // epilogue
#pragma unroll
    for (int i = 0; i < 8; i++) {
        size_t m = (size_t)(m0 + ty * 8 + i);
        float* crow = C + m * N + n0 + tx * 8;
        const float* brow = bias + n0 + tx * 8;
#pragma unroll
        for (int j0 = 0; j0 < 8; j0 += 4) {
            float4 bv = *(const float4*)(brow + j0);
            float4 cv;
            if (accum) {
                float4 old = *(const float4*)(crow + j0);
                cv.x = acc[i][j0 + 0] + bv.x + old.x;
                cv.y = acc[i][j0 + 1] + bv.y + old.y;
                cv.z = acc[i][j0 + 2] + bv.z + old.z;
                cv.w = acc[i][j0 + 3] + bv.w + old.w;
            } else {
                cv.x = acc[i][j0 + 0] + bv.x;
                cv.y = acc[i][j0 + 1] + bv.y;
                cv.z = acc[i][j0 + 2] + bv.z;
                cv.w = acc[i][j0 + 3] + bv.w;
            }
            *(float4*)(crow + j0) = cv;
        }
    }
}

// ============================================================
// Kernel 3: flash attention over packed qkv buffer [NROWS, 3*DMODEL].
//   q cols: h*64          k cols: DMODEL + h*64      v cols: 2*DMODEL + h*64
// grid = (NQT, NHEAD, BATCH), 256 threads, 64-query tile.
// is_local: KV range = [max(0,qt-1)*64, (qt+1)*64)  (chunk attends prev+self;
//           chunk 0's masked "prev" keys are exactly equivalent to omitting them)
// global:   KV range = [0, SLEN)
// smem (dynamic, 49664 B): Qst[64][65] d-major, Kst[64][65] d-major (reused as
// P[64][65] after scores), Vs[64][64] row-major.
// ============================================================
#define FA_STRIDE 65
#define FA_SMEM_BYTES ((64 * FA_STRIDE * 2 + 64 * 64) * 4)

__global__ __launch_bounds__(256) void flash_kernel(
    const float* __restrict__ qkv, float* __restrict__ out, int is_local)
{
    extern __shared__ float sm[];
    float* Qst = sm;                         // [64][65] : Qst[d][r]
    float* Kst = sm + 64 * FA_STRIDE;        // [64][65] : Kst[d][c]  / later P[r][c]
    float* Vs  = sm + 2 * 64 * FA_STRIDE;    // [64][64] : Vs[c][d]

    int qt = blockIdx.x;
    int h  = blockIdx.y;
    int b  = blockIdx.z;
    int q0 = qt * 64;

    const float* base = qkv + (size_t)b * SLEN * QKVD;
    int qoff = h * DHEAD;
    int koff = DMODEL + h * DHEAD;
    int voff = 2 * DMODEL + h * DHEAD;

    int tid = threadIdx.x;
    int ty = tid >> 4;       // 0..15 -> 4 query rows ty*4..ty*4+3
    int tx = tid & 15;       // 0..15 -> 4 dh/key cols tx*4..tx*4+3

    // ---- load Q tile transposed (d-major) ----
#pragma unroll
    for (int i = 0; i < 4; i++) {
        int linear = tid + i * 256;          // float4 index within 64x64 tile
        int r = linear >> 4;
        int d = (linear & 15) * 4;
        float4 q4 = *(const float4*)(base + (size_t)(q0 + r) * QKVD + qoff + d);
        Qst[(d + 0) * FA_STRIDE + r] = q4.x;
        Qst[(d + 1) * FA_STRIDE + r] = q4.y;
        Qst[(d + 2) * FA_STRIDE + r] = q4.z;
        Qst[(d + 3) * FA_STRIDE + r] = q4.w;
    }

    float m_i[4], l_i[4], o[4][4];
#pragma unroll
    for (int i = 0; i < 4; i++) {
        m_i[i] = -1e30f; l_i[i] = 0.f;
#pragma unroll
        for (int j = 0; j < 4; j++) o[i][j] = 0.f;
    }

    int kt0, kt1;
    if (is_local) { kt0 = (qt > 0) ? (qt - 1) : 0; kt1 = qt; }
    else          { kt0 = 0; kt1 = NQT - 1; }

    for (int kt = kt0; kt <= kt1; kt++) {
        __syncthreads();   // prior-iteration consumers done (also covers Q store)
        int k0 = kt * 64;
        // ---- load K (transposed) and V (direct) tiles ----
#pragma unroll
        for (int i = 0; i < 4; i++) {
            int linear = tid + i * 256;
            int r = linear >> 4;
            int d = (linear & 15) * 4;
            const float* krow = base + (size_t)(k0 + r) * QKVD;
            float4 k4 = *(const float4*)(krow + koff + d);
            Kst[(d + 0) * FA_STRIDE + r] = k4.x;
            Kst[(d + 1) * FA_STRIDE + r] = k4.y;
            Kst[(d + 2) * FA_STRIDE + r] = k4.z;
            Kst[(d + 3) * FA_STRIDE + r] = k4.w;
            float4 v4 = *(const float4*)(krow + voff + d);
            *(float4*)&Vs[r * 64 + d] = v4;
        }
        __syncthreads();

        // ---- S = scale * Q K^T  (each thread: 4x4 of the 64x64 score tile) ----
        float s[4][4];
#pragma unroll
        for (int i = 0; i < 4; i++)
#pragma unroll
            for (int j = 0; j < 4; j++) s[i][j] = 0.f;

#pragma unroll 4
        for (int k = 0; k < 64; k++) {
            float qv[4], kv[4];
#pragma unroll
            for (int i = 0; i < 4; i++) qv[i] = Qst[k * FA_STRIDE + ty * 4 + i];
#pragma unroll
            for (int j = 0; j < 4; j++) kv[j] = Kst[k * FA_STRIDE + tx * 4 + j];
#pragma unroll
            for (int i = 0; i < 4; i++)
#pragma unroll
                for (int j = 0; j < 4; j++)
                    s[i][j] += qv[i] * kv[j];
        }

        // ---- online softmax update (row groups = 16 threads sharing ty) ----
#pragma unroll
        for (int i = 0; i < 4; i++) {
            float rm = fmaxf(fmaxf(s[i][0], s[i][1]), fmaxf(s[i][2], s[i][3])) * 1.0f;
            // scores still unscaled: apply scale now
            float sc0 = s[i][0] * ATT_SCALE, sc1 = s[i][1] * ATT_SCALE;
            float sc2 = s[i][2] * ATT_SCALE, sc3 = s[i][3] * ATT_SCALE;
            rm = fmaxf(fmaxf(sc0, sc1), fmaxf(sc2, sc3));
#pragma unroll
            for (int off = 8; off > 0; off >>= 1)
                rm = fmaxf(rm, __shfl_xor_sync(0xffffffffu, rm, off));
            float mnew = fmaxf(m_i[i], rm);
            float corr = __expf(m_i[i] - mnew);
            m_i[i] = mnew;
            float p0 = __expf(sc0 - mnew);
            float p1 = __expf(sc1 - mnew);
            float p2 = __expf(sc2 - mnew);
            float p3 = __expf(sc3 - mnew);
            s[i][0] = p0; s[i][1] = p1; s[i][2] = p2; s[i][3] = p3;
            float rs = p0 + p1 + p2 + p3;
#pragma unroll
            for (int off = 8; off > 0; off >>= 1)
                rs += __shfl_xor_sync(0xffffffffu, rs, off);
            l_i[i] = l_i[i] * corr + rs;
#pragma unroll
            for (int j = 0; j < 4; j++) o[i][j] *= corr;
        }

        __syncthreads();   // all K reads done before P overwrites Kst
        // ---- write P into Kst buffer as P[r][c] ----
#pragma unroll
        for (int i = 0; i < 4; i++)
#pragma unroll
            for (int j = 0; j < 4; j++)
                Kst[(ty * 4 + i) * FA_STRIDE + tx * 4 + j] = s[i][j];
        __syncthreads();

        // ---- O += P V  (thread: rows ty*4.., dh cols tx*4..) ----
#pragma unroll 4
        for (int c = 0; c < 64; c++) {
            float4 v4 = *(const float4*)&Vs[c * 64 + tx * 4];
            float pr[4];
#pragma unroll
            for (int i = 0; i < 4; i++) pr[i] = Kst[(ty * 4 + i) * FA_STRIDE + c];
#pragma unroll
            for (int i = 0; i < 4; i++) {
                o[i][0] += pr[i] * v4.x;
                o[i][1] += pr[i] * v4.y;
                o[i][2] += pr[i] * v4.z;
                o[i][3] += pr[i] * v4.w;
            }
        }
    }

    // ---- finalize: O /= l, write to (B*S, D) layout at head offset ----
#pragma unroll
    for (int i = 0; i < 4; i++) {
        float inv = 1.f / l_i[i];
        int r = q0 + ty * 4 + i;
        float4 res;
        res.x = o[i][0] * inv; res.y = o[i][1] * inv;
        res.z = o[i][2] * inv; res.w = o[i][3] * inv;
        *(float4*)&out[((size_t)(b * SLEN + r)) * DMODEL + h * DHEAD + tx * 4] = res;
    }
}

// ============================================================
// host launcher
// ============================================================
extern "C" void kernel_launch(void* const* d_in, const int* in_sizes, int n_in,
                              void* d_out, int out_size)
{
    const float* x      = (const float*)d_in[0];
    const float* ln_l_g = (const float*)d_in[1];
    const float* ln_l_b = (const float*)d_in[2];
    const float* Wqkv_l = (const float*)d_in[3];
    const float* bqkv_l = (const float*)d_in[4];
    const float* Wo_l   = (const float*)d_in[5];
    const float* bo_l   = (const float*)d_in[6];
    const float* ln_g_g = (const float*)d_in[7];
    const float* ln_g_b = (const float*)d_in[8];
    const float* Wqkv_g = (const float*)d_in[9];
    const float* bqkv_g = (const float*)d_in[10];
    const float* Wo_g   = (const float*)d_in[11];
    const float* bo_g   = (const float*)d_in[12];
    float* out = (float*)d_out;

    float *xn_l, *xn_g, *qkv_l, *qkv_g, *ao_l, *ao_g;
    cudaGetSymbolAddress((void**)&xn_l, g_xn_l);
    cudaGetSymbolAddress((void**)&xn_g, g_xn_g);
    cudaGetSymbolAddress((void**)&qkv_l, g_qkv_l);
    cudaGetSymbolAddress((void**)&qkv_g, g_qkv_g);
    cudaGetSymbolAddress((void**)&ao_l, g_ao_l);
    cudaGetSymbolAddress((void**)&ao_g, g_ao_g);

    cudaFuncSetAttribute(flash_kernel,
                         cudaFuncAttributeMaxDynamicSharedMemorySize,
                         FA_SMEM_BYTES);

    // 1) fused dual LayerNorm
    ln_dual_kernel<<<NROWS, 256>>>(x, ln_l_g, ln_l_b, ln_g_g, ln_g_b, xn_l, xn_g);

    // 2) QKV projections
    dim3 gq(QKVD / BN, NROWS / BM);
    sgemm_tn<<<gq, 256>>>(xn_l, Wqkv_l, bqkv_l, qkv_l, NROWS, QKVD, DMODEL, 0);
    sgemm_tn<<<gq, 256>>>(xn_g, Wqkv_g, bqkv_g, qkv_g, NROWS, QKVD, DMODEL, 0);

    // 3) attention (local = restricted KV range, global = full)
    dim3 gf(NQT, NHEAD, BATCH);
    flash_kernel<<<gf, 256, FA_SMEM_BYTES>>>(qkv_l, ao_l, 1);
    flash_kernel<<<gf, 256, FA_SMEM_BYTES>>>(qkv_g, ao_g, 0);

    // 4) output projections, summed into d_out
    dim3 go(DMODEL / BN, NROWS / BM);
    sgemm_tn<<<go, 256>>>(ao_l, Wo_l, bo_l, out, NROWS, DMODEL, DMODEL, 0);
    sgemm_tn<<<go, 256>>>(ao_g, Wo_g, bo_g, out, NROWS, DMODEL, DMODEL, 1);
}

// round 5
// speedup vs baseline: 1.4054x; 1.4054x over previous
#include <cuda_runtime.h>
#include <cuda_bf16.h>
#include <math.h>
#include <stdint.h>

// ---------------- problem constants ----------------
#define BATCH   2
#define SLEN    2048
#define DMODEL  1024
#define NHEAD   16
#define DHEAD   64
#define NROWS   (BATCH * SLEN)          // 4096
#define QKVD    (3 * DMODEL)            // 3072
#define KCAT    (2 * DMODEL)            // 2048
#define NQT     (SLEN / 64)             // 32
#define ATT_SCALE 0.125f

// ---------------- scratch (device globals) ----------------
__device__ __align__(16) __nv_bfloat16 g_xlh[NROWS * DMODEL];
__device__ __align__(16) __nv_bfloat16 g_xll[NROWS * DMODEL];
__device__ __align__(16) __nv_bfloat16 g_xgh[NROWS * DMODEL];
__device__ __align__(16) __nv_bfloat16 g_xgl[NROWS * DMODEL];
__device__ __align__(16) float g_qkv_l[(size_t)NROWS * QKVD];
__device__ __align__(16) float g_qkv_g[(size_t)NROWS * QKVD];
__device__ __align__(16) __nv_bfloat16 g_wqkvl_h[QKVD * DMODEL];
__device__ __align__(16) __nv_bfloat16 g_wqkvl_l[QKVD * DMODEL];
__device__ __align__(16) __nv_bfloat16 g_wqkvg_h[QKVD * DMODEL];
__device__ __align__(16) __nv_bfloat16 g_wqkvg_l[QKVD * DMODEL];
__device__ __align__(16) __nv_bfloat16 g_wo_h[DMODEL * KCAT];
__device__ __align__(16) __nv_bfloat16 g_wo_l[DMODEL * KCAT];
__device__ __align__(16) __nv_bfloat16 g_aoh[(size_t)NROWS * KCAT];
__device__ __align__(16) __nv_bfloat16 g_aol[(size_t)NROWS * KCAT];

__device__ __forceinline__ uint32_t smem_u32(const void* p) {
    uint32_t a;
    asm("{ .reg .u64 t; cvta.to.shared.u64 t, %1; cvt.u32.u64 %0, t; }" : "=r"(a) : "l"(p));
    return a;
}

// ============================================================
// Kernel 1: fused dual LayerNorm -> bf16 hi/lo for both branches
// ============================================================
__global__ __launch_bounds__(256) void ln_dual_kernel(
    const float* __restrict__ x,
    const float* __restrict__ gl, const float* __restrict__ bl,
    const float* __restrict__ gg, const float* __restrict__ bg,
    __nv_bfloat16* __restrict__ xlh, __nv_bfloat16* __restrict__ xll,
    __nv_bfloat16* __restrict__ xgh, __nv_bfloat16* __restrict__ xgl)
{
    int row = blockIdx.x;
    const float* xr = x + (size_t)row * DMODEL;
    int t = threadIdx.x;

    float v[4];
    float s = 0.f, s2 = 0.f;
#pragma unroll
    for (int i = 0; i < 4; i++) {
        float a = xr[t + i * 256];
        v[i] = a; s += a; s2 += a * a;
    }
#pragma unroll
    for (int o = 16; o > 0; o >>= 1) {
        s  += __shfl_xor_sync(0xffffffffu, s,  o);
        s2 += __shfl_xor_sync(0xffffffffu, s2, o);
    }
    __shared__ float red0[8], red1[8], stat[2];
    int warp = t >> 5, lane = t & 31;
    if (lane == 0) { red0[warp] = s; red1[warp] = s2; }
    __syncthreads();
    if (t < 32) {
        float a = (t < 8) ? red0[t] : 0.f;
        float b = (t < 8) ? red1[t] : 0.f;
#pragma unroll
        for (int o = 4; o > 0; o >>= 1) {
            a += __shfl_xor_sync(0xffffffffu, a, o);
            b += __shfl_xor_sync(0xffffffffu, b, o);
        }
        if (t == 0) {
            float mean = a * (1.f / DMODEL);
            float var  = b * (1.f / DMODEL) - mean * mean;
            stat[0] = mean;
            stat[1] = rsqrtf(var + 1e-5f);
        }
    }
    __syncthreads();
    float mean = stat[0], rstd = stat[1];
    size_t rb = (size_t)row * DMODEL;
#pragma unroll
    for (int i = 0; i < 4; i++) {
        int c = t + i * 256;
        float n = (v[i] - mean) * rstd;
        float al = n * gl[c] + bl[c];
        float ag = n * gg[c] + bg[c];
        __nv_bfloat16 hl = __float2bfloat16(al);
        __nv_bfloat16 hg = __float2bfloat16(ag);
        xlh[rb + c] = hl;
        xll[rb + c] = __float2bfloat16(al - __bfloat162float(hl));
        xgh[rb + c] = hg;
        xgl[rb + c] = __float2bfloat16(ag - __bfloat162float(hg));
    }
}

// ============================================================
// Kernel 2: weight split fp32 -> bf16 hi/lo (remapped destination)
// ============================================================
__global__ __launch_bounds__(256) void convert_split(
    const float* __restrict__ src, __nv_bfloat16* __restrict__ h,
    __nv_bfloat16* __restrict__ l, int cols4, int dstride, int doff, int total4)
{
    int idx = blockIdx.x * 256 + threadIdx.x;
    if (idx >= total4) return;
    int r = idx / cols4;
    int c4 = idx - r * cols4;
    float4 v = ((const float4*)src)[idx];
    size_t d = (size_t)r * dstride + doff + c4 * 4;
    float vv[4] = {v.x, v.y, v.z, v.w};
#pragma unroll
    for (int j = 0; j < 4; j++) {
        __nv_bfloat16 hi = __float2bfloat16(vv[j]);
        h[d + j] = hi;
        l[d + j] = __float2bfloat16(vv[j] - __bfloat162float(hi));
    }
}

// ============================================================
// Kernel 3: bf16 3-term-split GEMM via mma.sync.m16n8k16 (HMMA)
//   C[M,Nt] = A x B^T + bias0 (+bias1); A=[M,K] k-contig, B=[N,K] k-contig.
//   Virtual K = 3K: phase 0: Ah*Bh, phase 1: Ah*Bl, phase 2: Al*Bh.
//   CTA 128x128, BK=64, cp.async double buffer, 8 warps of 64x32.
// ============================================================
#define GBM 128
#define GBN 128
#define GBK 64
#define SAPAD 72                           // bf16 elems per smem row (144B)
#define TILE_SB (128 * SAPAD * 2)          // 18432 B per tile
#define STAGE_SB (2 * TILE_SB)             // A + B
#define GEMM_SMEM (2 * STAGE_SB)           // 73728 B

#define LDSM_X4(r0, r1, r2, r3, a) \
    asm volatile("ldmatrix.sync.aligned.m8n8.x4.shared.b16 {%0,%1,%2,%3}, [%4];" \
                 : "=r"(r0), "=r"(r1), "=r"(r2), "=r"(r3) : "r"(a))

#define MMA16816(c, a, b) \
    asm volatile("mma.sync.aligned.m16n8k16.row.col.f32.bf16.bf16.f32 " \
                 "{%0,%1,%2,%3}, {%4,%5,%6,%7}, {%8,%9}, {%0,%1,%2,%3};" \
                 : "+f"((c)[0]), "+f"((c)[1]), "+f"((c)[2]), "+f"((c)[3]) \
                 : "r"((a)[0]), "r"((a)[1]), "r"((a)[2]), "r"((a)[3]), \
                   "r"((b)[0]), "r"((b)[1]))

#define CP_ASYNC16(s, g) \
    asm volatile("cp.async.cg.shared.global [%0], [%1], 16;" :: "r"(s), "l"(g))
#define CP_COMMIT() asm volatile("cp.async.commit_group;")
#define CP_WAIT0()  asm volatile("cp.async.wait_group 0;")

__global__ __launch_bounds__(256, 2) void gemm3bf16(
    const __nv_bfloat16* __restrict__ Ah, const __nv_bfloat16* __restrict__ Al,
    const __nv_bfloat16* __restrict__ Bh, const __nv_bfloat16* __restrict__ Bl,
    const float* __restrict__ bias0, const float* __restrict__ bias1,
    float* __restrict__ C, int Ntotal, int K)
{
    extern __shared__ char gsm[];
    uint32_t sbase = smem_u32(gsm);

    int tid = threadIdx.x;
    int m0 = blockIdx.y * GBM;
    int n0 = blockIdx.x * GBN;
    int lane = tid & 31;
    int wid = tid >> 5;
    int warp_m = (wid >> 2) * 64;
    int warp_n = (wid & 3) * 32;

    int kslabs = K >> 6;          // slabs per phase
    int nslab = 3 * kslabs;

    // per-thread loader assignment: 8 chunks of 16B; first 4 -> A tile, next 4 -> B tile
    // chunk id c in [0,1024): row=c>>3, col16=c&7
    int lc0 = tid * 4;            // A chunks [lc0, lc0+4)

    float acc[4][4][4];
#pragma unroll
    for (int i = 0; i < 4; i++)
#pragma unroll
        for (int j = 0; j < 4; j++)
#pragma unroll
            for (int q = 0; q < 4; q++) acc[i][j][q] = 0.f;

    // ldmatrix address offsets (within a tile) — invariant across slabs
    uint32_t a_off[4], b_off[2];
#pragma unroll
    for (int i = 0; i < 4; i++)
        a_off[i] = (uint32_t)((warp_m + 16 * i + (lane & 15)) * (SAPAD * 2) + (lane >> 4) * 16);
#pragma unroll
    for (int j = 0; j < 2; j++)
        b_off[j] = (uint32_t)((warp_n + 16 * j + (lane & 7) + ((lane & 16) >> 1)) * (SAPAD * 2)
                              + (lane & 8) * 2);

    // ---- loader lambda (macro-style) ----
    auto load_slab = [&](int s, int buf) {
        int ph = s / kslabs;
        int ks = (s - ph * kslabs) << 6;
        const __nv_bfloat16* As = (ph < 2) ? Ah : Al;
        const __nv_bfloat16* Bs = (ph == 1) ? Bl : Bh;
        uint32_t sa = sbase + buf * STAGE_SB;
        uint32_t sb = sa + TILE_SB;
#pragma unroll
        for (int q = 0; q < 4; q++) {
            int c = lc0 + q;
            int row = c >> 3, col = c & 7;
            CP_ASYNC16(sa + row * (SAPAD * 2) + col * 16,
                       As + (size_t)(m0 + row) * K + ks + col * 8);
        }
#pragma unroll
        for (int q = 0; q < 4; q++) {
            int c = lc0 + q;
            int row = c >> 3, col = c & 7;
            CP_ASYNC16(sb + row * (SAPAD * 2) + col * 16,
                       Bs + (size_t)(n0 + row) * K + ks + col * 8);
        }
        CP_COMMIT();
    };

    load_slab(0, 0);

    for (int s = 0; s < nslab; s++) {
        CP_WAIT0();
        __syncthreads();
        if (s + 1 < nslab) load_slab(s + 1, (s + 1) & 1);

        uint32_t sa = sbase + (s & 1) * STAGE_SB;
        uint32_t sb = sa + TILE_SB;
#pragma unroll
        for (int kk = 0; kk < 4; kk++) {
            uint32_t a[4][4];
#pragma unroll
            for (int i = 0; i < 4; i++)
                LDSM_X4(a[i][0], a[i][1], a[i][2], a[i][3], sa + a_off[i] + kk * 32);
            uint32_t b[4][2];
#pragma unroll
            for (int j = 0; j < 2; j++) {
                uint32_t t0, t1, t2, t3;
                LDSM_X4(t0, t1, t2, t3, sb + b_off[j] + kk * 32);
                b[2 * j][0] = t0; b[2 * j][1] = t1;
                b[2 * j + 1][0] = t2; b[2 * j + 1][1] = t3;
            }
#pragma unroll
            for (int i = 0; i < 4; i++)
#pragma unroll
                for (int j = 0; j < 4; j++)
                    MMA16816(acc[i][j], a[i], b[j]);
        }
    }

    // ---- epilogue ----
#pragma unroll
    for (int i = 0; i < 4; i++) {
        int r0 = m0 + warp_m + 16 * i + (lane >> 2);
#pragma unroll
        for (int j = 0; j < 4; j++) {
            int col = n0 + warp_n + 8 * j + (lane & 3) * 2;
            float b0v = bias0[col], b1v = bias0[col + 1];
            if (bias1) { b0v += bias1[col]; b1v += bias1[col + 1]; }
            float2* p0 = (float2*)(C + (size_t)r0 * Ntotal + col);
            float2* p1 = (float2*)(C + (size_t)(r0 + 8) * Ntotal + col);
            float2 v0; v0.x = acc[i][j][0] + b0v; v0.y = acc[i][j][1] + b1v;
            float2 v1; v1.x = acc[i][j][2] + b0v; v1.y = acc[i][j][3] + b1v;
            *p0 = v0;
            *p1 = v1;
        }
    }
}

// ============================================================
// Kernel 4: flash attention (fp32); writes bf16 hi/lo into cat'd ao buffer.
// ============================================================
#define FA_STRIDE 65
#define FA_SMEM_BYTES ((64 * FA_STRIDE * 2 + 64 * 64) * 4)

__global__ __launch_bounds__(256) void flash_kernel(
    const float* __restrict__ qkv,
    __nv_bfloat16* __restrict__ aoh, __nv_bfloat16* __restrict__ aol,
    int is_local)
{
    extern __shared__ float sm[];
    float* Qst = sm;
    float* Kst = sm + 64 * FA_STRIDE;
    float* Vs  = sm + 2 * 64 * FA_STRIDE;

    int qt = blockIdx.x;
    int h  = blockIdx.y;
    int b  = blockIdx.z;
    int q0 = qt * 64;

    const float* base = qkv + (size_t)b * SLEN * QKVD;
    int qoff = h * DHEAD;
    int koff = DMODEL + h * DHEAD;
    int voff = 2 * DMODEL + h * DHEAD;

    int tid = threadIdx.x;
    int ty = tid >> 4;
    int tx = tid & 15;

#pragma unroll
    for (int i = 0; i < 4; i++) {
        int linear = tid + i * 256;
        int r = linear >> 4;
        int d = (linear & 15) * 4;
        float4 q4 = *(const float4*)(base + (size_t)(q0 + r) * QKVD + qoff + d);
        Qst[(d + 0) * FA_STRIDE + r] = q4.x;
        Qst[(d + 1) * FA_STRIDE + r] = q4.y;
        Qst[(d + 2) * FA_STRIDE + r] = q4.z;
        Qst[(d + 3) * FA_STRIDE + r] = q4.w;
    }

    float m_i[4], l_i[4], o[4][4];
#pragma unroll
    for (int i = 0; i < 4; i++) {
        m_i[i] = -1e30f; l_i[i] = 0.f;
#pragma unroll
        for (int j = 0; j < 4; j++) o[i][j] = 0.f;
    }

    int kt0, kt1;
    if (is_local) { kt0 = (qt > 0) ? (qt - 1) : 0; kt1 = qt; }
    else          { kt0 = 0; kt1 = NQT - 1; }

    for (int kt = kt0; kt <= kt1; kt++) {
        __syncthreads();
        int k0 = kt * 64;
#pragma unroll
        for (int i = 0; i < 4; i++) {
            int linear = tid + i * 256;
            int r = linear >> 4;
            int d = (linear & 15) * 4;
            const float* krow = base + (size_t)(k0 + r) * QKVD;
            float4 k4 = *(const float4*)(krow + koff + d);
            Kst[(d + 0) * FA_STRIDE + r] = k4.x;
            Kst[(d + 1) * FA_STRIDE + r] = k4.y;
            Kst[(d + 2) * FA_STRIDE + r] = k4.z;
            Kst[(d + 3) * FA_STRIDE + r] = k4.w;
            float4 v4 = *(const float4*)(krow + voff + d);
            *(float4*)&Vs[r * 64 + d] = v4;
        }
        __syncthreads();

        float s[4][4];
#pragma unroll
        for (int i = 0; i < 4; i++)
#pragma unroll
            for (int j = 0; j < 4; j++) s[i][j] = 0.f;

#pragma unroll 4
        for (int k = 0; k < 64; k++) {
            float qv[4], kv[4];
#pragma unroll
            for (int i = 0; i < 4; i++) qv[i] = Qst[k * FA_STRIDE + ty * 4 + i];
#pragma unroll
            for (int j = 0; j < 4; j++) kv[j] = Kst[k * FA_STRIDE + tx * 4 + j];
#pragma unroll
            for (int i = 0; i < 4; i++)
#pragma unroll
                for (int j = 0; j < 4; j++)
                    s[i][j] += qv[i] * kv[j];
        }

#pragma unroll
        for (int i = 0; i < 4; i++) {
            float sc0 = s[i][0] * ATT_SCALE, sc1 = s[i][1] * ATT_SCALE;
            float sc2 = s[i][2] * ATT_SCALE, sc3 = s[i][3] * ATT_SCALE;
            float rm = fmaxf(fmaxf(sc0, sc1), fmaxf(sc2, sc3));
#pragma unroll
            for (int off = 8; off > 0; off >>= 1)
                rm = fmaxf(rm, __shfl_xor_sync(0xffffffffu, rm, off));
            float mnew = fmaxf(m_i[i], rm);
            float corr = __expf(m_i[i] - mnew);
            m_i[i] = mnew;
            float p0 = __expf(sc0 - mnew);
            float p1 = __expf(sc1 - mnew);
            float p2 = __expf(sc2 - mnew);
            float p3 = __expf(sc3 - mnew);
            s[i][0] = p0; s[i][1] = p1; s[i][2] = p2; s[i][3] = p3;
            float rs = p0 + p1 + p2 + p3;
#pragma unroll
            for (int off = 8; off > 0; off >>= 1)
                rs += __shfl_xor_sync(0xffffffffu, rs, off);
            l_i[i] = l_i[i] * corr + rs;
#pragma unroll
            for (int j = 0; j < 4; j++) o[i][j] *= corr;
        }

        __syncthreads();
#pragma unroll
        for (int i = 0; i < 4; i++)
#pragma unroll
            for (int j = 0; j < 4; j++)
                Kst[(ty * 4 + i) * FA_STRIDE + tx * 4 + j] = s[i][j];
        __syncthreads();

#pragma unroll 4
        for (int c = 0; c < 64; c++) {
            float4 v4 = *(const float4*)&Vs[c * 64 + tx * 4];
            float pr[4];
#pragma unroll
            for (int i = 0; i < 4; i++) pr[i] = Kst[(ty * 4 + i) * FA_STRIDE + c];
#pragma unroll
            for (int i = 0; i < 4; i++) {
                o[i][0] += pr[i] * v4.x;
                o[i][1] += pr[i] * v4.y;
                o[i][2] += pr[i] * v4.z;
                o[i][3] += pr[i] * v4.w;
            }
        }
    }

    int colofs = is_local ? 0 : DMODEL;
#pragma unroll
    for (int i = 0; i < 4; i++) {
        float inv = 1.f / l_i[i];
        int r = q0 + ty * 4 + i;
        size_t dbase = (size_t)(b * SLEN + r) * KCAT + colofs + h * DHEAD + tx * 4;
#pragma unroll
        for (int j = 0; j < 4; j++) {
            float val = o[i][j] * inv;
            __nv_bfloat16 hi = __float2bfloat16(val);
            aoh[dbase + j] = hi;
            aol[dbase + j] = __float2bfloat16(val - __bfloat162float(hi));
        }
    }
}

// ============================================================
// host launcher
// ============================================================
extern "C" void kernel_launch(void* const* d_in, const int* in_sizes, int n_in,
                              void* d_out, int out_size)
{
    const float* x      = (const float*)d_in[0];
    const float* ln_l_g = (const float*)d_in[1];
    const float* ln_l_b = (const float*)d_in[2];
    const float* Wqkv_l = (const float*)d_in[3];
    const float* bqkv_l = (const float*)d_in[4];
    const float* Wo_l   = (const float*)d_in[5];
    const float* bo_l   = (const float*)d_in[6];
    const float* ln_g_g = (const float*)d_in[7];
    const float* ln_g_b = (const float*)d_in[8];
    const float* Wqkv_g = (const float*)d_in[9];
    const float* bqkv_g = (const float*)d_in[10];
    const float* Wo_g   = (const float*)d_in[11];
    const float* bo_g   = (const float*)d_in[12];
    float* out = (float*)d_out;

    __nv_bfloat16 *xlh, *xll, *xgh, *xgl, *wqlh, *wqll, *wqgh, *wqgl, *woh, *wol, *aoh, *aol;
    float *qkv_l, *qkv_g;
    cudaGetSymbolAddress((void**)&xlh, g_xlh);
    cudaGetSymbolAddress((void**)&xll, g_xll);
    cudaGetSymbolAddress((void**)&xgh, g_xgh);
    cudaGetSymbolAddress((void**)&xgl, g_xgl);
    cudaGetSymbolAddress((void**)&qkv_l, g_qkv_l);
    cudaGetSymbolAddress((void**)&qkv_g, g_qkv_g);
    cudaGetSymbolAddress((void**)&wqlh, g_wqkvl_h);
    cudaGetSymbolAddress((void**)&wqll, g_wqkvl_l);
    cudaGetSymbolAddress((void**)&wqgh, g_wqkvg_h);
    cudaGetSymbolAddress((void**)&wqgl, g_wqkvg_l);
    cudaGetSymbolAddress((void**)&woh, g_wo_h);
    cudaGetSymbolAddress((void**)&wol, g_wo_l);
    cudaGetSymbolAddress((void**)&aoh, g_aoh);
    cudaGetSymbolAddress((void**)&aol, g_aol);

    cudaFuncSetAttribute(flash_kernel, cudaFuncAttributeMaxDynamicSharedMemorySize, FA_SMEM_BYTES);
    cudaFuncSetAttribute(gemm3bf16, cudaFuncAttributeMaxDynamicSharedMemorySize, GEMM_SMEM);

    // 1) dual LN -> bf16 hi/lo
    ln_dual_kernel<<<NROWS, 256>>>(x, ln_l_g, ln_l_b, ln_g_g, ln_g_b, xlh, xll, xgh, xgl);

    // 2) weight splits
    {
        int t4 = QKVD * DMODEL / 4;
        convert_split<<<(t4 + 255) / 256, 256>>>(Wqkv_l, wqlh, wqll, DMODEL / 4, DMODEL, 0, t4);
        convert_split<<<(t4 + 255) / 256, 256>>>(Wqkv_g, wqgh, wqgl, DMODEL / 4, DMODEL, 0, t4);
        int t4o = DMODEL * DMODEL / 4;
        convert_split<<<(t4o + 255) / 256, 256>>>(Wo_l, woh, wol, DMODEL / 4, KCAT, 0, t4o);
        convert_split<<<(t4o + 255) / 256, 256>>>(Wo_g, woh, wol, DMODEL / 4, KCAT, DMODEL, t4o);
    }

    // 3) QKV projections (HMMA split GEMM)
    {
        dim3 g(QKVD / GBN, NROWS / GBM);
        gemm3bf16<<<g, 256, GEMM_SMEM>>>(xlh, xll, wqlh, wqll, bqkv_l, nullptr, qkv_l, QKVD, DMODEL);
        gemm3bf16<<<g, 256, GEMM_SMEM>>>(xgh, xgl, wqgh, wqgl, bqkv_g, nullptr, qkv_g, QKVD, DMODEL);
    }

    // 4) attention -> bf16 hi/lo into concatenated activation
    {
        dim3 gf(NQT, NHEAD, BATCH);
        flash_kernel<<<gf, 256, FA_SMEM_BYTES>>>(qkv_l, aoh, aol, 1);
        flash_kernel<<<gf, 256, FA_SMEM_BYTES>>>(qkv_g, aoh, aol, 0);
    }

    // 5) fused out-projection: [ao_l|ao_g] x [Wo_l|Wo_g]^T + bo_l + bo_g
    {
        dim3 g(DMODEL / GBN, NROWS / GBM);
        gemm3bf16<<<g, 256, GEMM_SMEM>>>(aoh, aol, woh, wol, bo_l, bo_g, out, DMODEL, KCAT);
    }
}

// round 6
// speedup vs baseline: 1.5339x; 1.0914x over previous
#include <cuda_runtime.h>
#include <cuda_bf16.h>
#include <math.h>
#include <stdint.h>

// ---------------- problem constants ----------------
#define BATCH   2
#define SLEN    2048
#define DMODEL  1024
#define NHEAD   16
#define DHEAD   64
#define NROWS   (BATCH * SLEN)          // 4096
#define QKVD    (3 * DMODEL)            // 3072
#define KCAT    (2 * DMODEL)            // 2048
#define NQT     (SLEN / 64)             // 32
#define ATT_SCALE 0.125f

// ---------------- scratch (device globals) ----------------
__device__ __align__(16) __nv_bfloat16 g_xlh[NROWS * DMODEL];
__device__ __align__(16) __nv_bfloat16 g_xll[NROWS * DMODEL];
__device__ __align__(16) __nv_bfloat16 g_xgh[NROWS * DMODEL];
__device__ __align__(16) __nv_bfloat16 g_xgl[NROWS * DMODEL];
__device__ __align__(16) float g_qkv_l[(size_t)NROWS * QKVD];
__device__ __align__(16) float g_qkv_g[(size_t)NROWS * QKVD];
__device__ __align__(16) __nv_bfloat16 g_wqkvl_h[QKVD * DMODEL];
__device__ __align__(16) __nv_bfloat16 g_wqkvl_l[QKVD * DMODEL];
__device__ __align__(16) __nv_bfloat16 g_wqkvg_h[QKVD * DMODEL];
__device__ __align__(16) __nv_bfloat16 g_wqkvg_l[QKVD * DMODEL];
__device__ __align__(16) __nv_bfloat16 g_wo_h[DMODEL * KCAT];
__device__ __align__(16) __nv_bfloat16 g_wo_l[DMODEL * KCAT];
__device__ __align__(16) __nv_bfloat16 g_aoh[(size_t)NROWS * KCAT];
__device__ __align__(16) __nv_bfloat16 g_aol[(size_t)NROWS * KCAT];

__device__ __forceinline__ uint32_t smem_u32(const void* p) {
    uint32_t a;
    asm("{ .reg .u64 t; cvta.to.shared.u64 t, %1; cvt.u32.u64 %0, t; }" : "=r"(a) : "l"(p));
    return a;
}

// ============================================================
// Kernel 1: fused dual LayerNorm -> bf16 hi/lo for both branches
// ============================================================
__global__ __launch_bounds__(256) void ln_dual_kernel(
    const float* __restrict__ x,
    const float* __restrict__ gl, const float* __restrict__ bl,
    const float* __restrict__ gg, const float* __restrict__ bg,
    __nv_bfloat16* __restrict__ xlh, __nv_bfloat16* __restrict__ xll,
    __nv_bfloat16* __restrict__ xgh, __nv_bfloat16* __restrict__ xgl)
{
    int row = blockIdx.x;
    const float* xr = x + (size_t)row * DMODEL;
    int t = threadIdx.x;

    float v[4];
    float s = 0.f, s2 = 0.f;
#pragma unroll
    for (int i = 0; i < 4; i++) {
        float a = xr[t + i * 256];
        v[i] = a; s += a; s2 += a * a;
    }
#pragma unroll
    for (int o = 16; o > 0; o >>= 1) {
        s  += __shfl_xor_sync(0xffffffffu, s,  o);
        s2 += __shfl_xor_sync(0xffffffffu, s2, o);
    }
    __shared__ float red0[8], red1[8], stat[2];
    int warp = t >> 5, lane = t & 31;
    if (lane == 0) { red0[warp] = s; red1[warp] = s2; }
    __syncthreads();
    if (t < 32) {
        float a = (t < 8) ? red0[t] : 0.f;
        float b = (t < 8) ? red1[t] : 0.f;
#pragma unroll
        for (int o = 4; o > 0; o >>= 1) {
            a += __shfl_xor_sync(0xffffffffu, a, o);
            b += __shfl_xor_sync(0xffffffffu, b, o);
        }
        if (t == 0) {
            float mean = a * (1.f / DMODEL);
            float var  = b * (1.f / DMODEL) - mean * mean;
            stat[0] = mean;
            stat[1] = rsqrtf(var + 1e-5f);
        }
    }
    __syncthreads();
    float mean = stat[0], rstd = stat[1];
    size_t rb = (size_t)row * DMODEL;
#pragma unroll
    for (int i = 0; i < 4; i++) {
        int c = t + i * 256;
        float n = (v[i] - mean) * rstd;
        float al = n * gl[c] + bl[c];
        float ag = n * gg[c] + bg[c];
        __nv_bfloat16 hl = __float2bfloat16(al);
        __nv_bfloat16 hg = __float2bfloat16(ag);
        xlh[rb + c] = hl;
        xll[rb + c] = __float2bfloat16(al - __bfloat162float(hl));
        xgh[rb + c] = hg;
        xgl[rb + c] = __float2bfloat16(ag - __bfloat162float(hg));
    }
}

// ============================================================
// Kernel 2: weight split fp32 -> bf16 hi/lo (remapped destination)
// ============================================================
__global__ __launch_bounds__(256) void convert_split(
    const float* __restrict__ src, __nv_bfloat16* __restrict__ h,
    __nv_bfloat16* __restrict__ l, int cols4, int dstride, int doff, int total4)
{
    int idx = blockIdx.x * 256 + threadIdx.x;
    if (idx >= total4) return;
    int r = idx / cols4;
    int c4 = idx - r * cols4;
    float4 v = ((const float4*)src)[idx];
    size_t d = (size_t)r * dstride + doff + c4 * 4;
    float vv[4] = {v.x, v.y, v.z, v.w};
#pragma unroll
    for (int j = 0; j < 4; j++) {
        __nv_bfloat16 hi = __float2bfloat16(vv[j]);
        h[d + j] = hi;
        l[d + j] = __float2bfloat16(vv[j] - __bfloat162float(hi));
    }
}

// ============================================================
// Kernel 3: bf16 3-term-split GEMM via mma.sync.m16n8k16 (HMMA)
//   Virtual K = 3K (phases AhBh, AhBl, AlBh). CTA 128x128, BK=64.
//   3-stage cp.async ring, XOR-swizzled 128B smem rows, 8 warps of 64x32.
// ============================================================
#define GBM 128
#define GBN 128
#define TILE_SB  16384                 // 128 rows x 128B
#define STAGE_SB 32768                 // A + B
#define NSTAGE   3
#define GEMM_SMEM (NSTAGE * STAGE_SB)  // 98304

#define LDSM_X4(r0, r1, r2, r3, a) \
    asm volatile("ldmatrix.sync.aligned.m8n8.x4.shared.b16 {%0,%1,%2,%3}, [%4];" \
                 : "=r"(r0), "=r"(r1), "=r"(r2), "=r"(r3) : "r"(a))

#define MMA16816(c, a, b) \
    asm volatile("mma.sync.aligned.m16n8k16.row.col.f32.bf16.bf16.f32 " \
                 "{%0,%1,%2,%3}, {%4,%5,%6,%7}, {%8,%9}, {%0,%1,%2,%3};" \
                 : "+f"((c)[0]), "+f"((c)[1]), "+f"((c)[2]), "+f"((c)[3]) \
                 : "r"((a)[0]), "r"((a)[1]), "r"((a)[2]), "r"((a)[3]), \
                   "r"((b)[0]), "r"((b)[1]))

#define CP_ASYNC16(s, g) \
    asm volatile("cp.async.cg.shared.global [%0], [%1], 16;" :: "r"(s), "l"(g))
#define CP_COMMIT() asm volatile("cp.async.commit_group;")
#define CP_WAIT1()  asm volatile("cp.async.wait_group 1;")

__global__ __launch_bounds__(256, 2) void gemm3bf16(
    const __nv_bfloat16* __restrict__ Ah, const __nv_bfloat16* __restrict__ Al,
    const __nv_bfloat16* __restrict__ Bh, const __nv_bfloat16* __restrict__ Bl,
    const float* __restrict__ bias0, const float* __restrict__ bias1,
    float* __restrict__ C, int Ntotal, int K)
{
    extern __shared__ char gsm[];
    uint32_t sbase = smem_u32(gsm);

    int tid = threadIdx.x;
    int m0 = blockIdx.y * GBM;
    int n0 = blockIdx.x * GBN;
    int lane = tid & 31;
    int wid = tid >> 5;
    int warp_m = (wid >> 2) * 64;
    int warp_n = (wid & 3) * 32;

    int kslabs = K >> 6;
    int nslab = 3 * kslabs;

    // loader geometry: 4 chunks of 16B per tile per thread
    int l_row = tid >> 1;                   // 0..127
    int l_c0  = (tid & 1) * 4;              // 0 or 4
    int l_sw  = l_row & 7;
    uint32_t l_sm_base = (uint32_t)(l_row * 128);

    float acc[4][4][4];
#pragma unroll
    for (int i = 0; i < 4; i++)
#pragma unroll
        for (int j = 0; j < 4; j++)
#pragma unroll
            for (int q = 0; q < 4; q++) acc[i][j][q] = 0.f;

    // ldmatrix geometry (swizzled): addr = rowbase + ((chunk ^ (row&7))<<4)
    uint32_t a_rb[4]; int a_rs[4];
#pragma unroll
    for (int i = 0; i < 4; i++) {
        int r = warp_m + 16 * i + (lane & 15);
        a_rb[i] = (uint32_t)(r * 128);
        a_rs[i] = r & 7;
    }
    uint32_t b_rb[2]; int b_rs[2];
#pragma unroll
    for (int j = 0; j < 2; j++) {
        int r = warp_n + 16 * j + (lane & 7) + ((lane & 16) >> 1);
        b_rb[j] = (uint32_t)(r * 128);
        b_rs[j] = r & 7;
    }
    int cA0 = (lane >> 4);          // 0..1
    int cB0 = ((lane >> 3) & 1);    // 0..1

    auto load_slab = [&](int s, int buf) {
        const __nv_bfloat16* As;
        const __nv_bfloat16* Bs;
        int ks;
        if (s < kslabs)          { As = Ah; Bs = Bh; ks = s << 6; }
        else if (s < 2 * kslabs) { As = Ah; Bs = Bl; ks = (s - kslabs) << 6; }
        else                     { As = Al; Bs = Bh; ks = (s - 2 * kslabs) << 6; }
        uint32_t sa = sbase + buf * STAGE_SB + l_sm_base;
        uint32_t sb = sa + TILE_SB;
        const __nv_bfloat16* ga = As + (size_t)(m0 + l_row) * K + ks + l_c0 * 8;
        const __nv_bfloat16* gb = Bs + (size_t)(n0 + l_row) * K + ks + l_c0 * 8;
#pragma unroll
        for (int q = 0; q < 4; q++) {
            int phys = ((l_c0 + q) ^ l_sw) << 4;
            CP_ASYNC16(sa + phys, ga + q * 8);
        }
#pragma unroll
        for (int q = 0; q < 4; q++) {
            int phys = ((l_c0 + q) ^ l_sw) << 4;
            CP_ASYNC16(sb + phys, gb + q * 8);
        }
    };

    load_slab(0, 0); CP_COMMIT();
    load_slab(1, 1); CP_COMMIT();

    int buf = 0;       // = s % 3
    int pbuf = 2;      // = (s+2) % 3
    for (int s = 0; s < nslab; s++) {
        CP_WAIT1();            // stage s complete (≤1 group pending)
        __syncthreads();       // all warps past stage s-1 compute; pbuf free

        if (s + 2 < nslab) load_slab(s + 2, pbuf);
        CP_COMMIT();

        uint32_t sa = sbase + buf * STAGE_SB;
        uint32_t sb = sa + TILE_SB;
#pragma unroll
        for (int kk = 0; kk < 4; kk++) {
            uint32_t a[4][4];
#pragma unroll
            for (int i = 0; i < 4; i++) {
                uint32_t ad = sa + a_rb[i] + (uint32_t)((((cA0 + 2 * kk) ^ a_rs[i])) << 4);
                LDSM_X4(a[i][0], a[i][1], a[i][2], a[i][3], ad);
            }
            uint32_t b[4][2];
#pragma unroll
            for (int j = 0; j < 2; j++) {
                uint32_t bd = sb + b_rb[j] + (uint32_t)((((cB0 + 2 * kk) ^ b_rs[j])) << 4);
                uint32_t t0, t1, t2, t3;
                LDSM_X4(t0, t1, t2, t3, bd);
                b[2 * j][0] = t0; b[2 * j][1] = t1;
                b[2 * j + 1][0] = t2; b[2 * j + 1][1] = t3;
            }
#pragma unroll
            for (int i = 0; i < 4; i++)
#pragma unroll
                for (int j = 0; j < 4; j++)
                    MMA16816(acc[i][j], a[i], b[j]);
        }

        buf = (buf == 2) ? 0 : buf + 1;
        pbuf = (pbuf == 2) ? 0 : pbuf + 1;
    }

    // ---- epilogue ----
#pragma unroll
    for (int i = 0; i < 4; i++) {
        int r0 = m0 + warp_m + 16 * i + (lane >> 2);
#pragma unroll
        for (int j = 0; j < 4; j++) {
            int col = n0 + warp_n + 8 * j + (lane & 3) * 2;
            float b0v = bias0[col], b1v = bias0[col + 1];
            if (bias1) { b0v += bias1[col]; b1v += bias1[col + 1]; }
            float2* p0 = (float2*)(C + (size_t)r0 * Ntotal + col);
            float2* p1 = (float2*)(C + (size_t)(r0 + 8) * Ntotal + col);
            float2 v0; v0.x = acc[i][j][0] + b0v; v0.y = acc[i][j][1] + b1v;
            float2 v1; v1.x = acc[i][j][2] + b0v; v1.y = acc[i][j][3] + b1v;
            *p0 = v0;
            *p1 = v1;
        }
    }
}

// ============================================================
// Kernel 4: flash attention (fp32); writes bf16 hi/lo into cat'd ao buffer.
// ============================================================
#define FA_STRIDE 65
#define FA_SMEM_BYTES ((64 * FA_STRIDE * 2 + 64 * 64) * 4)

__global__ __launch_bounds__(256) void flash_kernel(
    const float* __restrict__ qkv,
    __nv_bfloat16* __restrict__ aoh, __nv_bfloat16* __restrict__ aol,
    int is_local)
{
    extern __shared__ float sm[];
    float* Qst = sm;
    float* Kst = sm + 64 * FA_STRIDE;
    float* Vs  = sm + 2 * 64 * FA_STRIDE;

    int qt = blockIdx.x;
    int h  = blockIdx.y;
    int b  = blockIdx.z;
    int q0 = qt * 64;

    const float* base = qkv + (size_t)b * SLEN * QKVD;
    int qoff = h * DHEAD;
    int koff = DMODEL + h * DHEAD;
    int voff = 2 * DMODEL + h * DHEAD;

    int tid = threadIdx.x;
    int ty = tid >> 4;
    int tx = tid & 15;

#pragma unroll
    for (int i = 0; i < 4; i++) {
        int linear = tid + i * 256;
        int r = linear >> 4;
        int d = (linear & 15) * 4;
        float4 q4 = *(const float4*)(base + (size_t)(q0 + r) * QKVD + qoff + d);
        Qst[(d + 0) * FA_STRIDE + r] = q4.x;
        Qst[(d + 1) * FA_STRIDE + r] = q4.y;
        Qst[(d + 2) * FA_STRIDE + r] = q4.z;
        Qst[(d + 3) * FA_STRIDE + r] = q4.w;
    }

    float m_i[4], l_i[4], o[4][4];
#pragma unroll
    for (int i = 0; i < 4; i++) {
        m_i[i] = -1e30f; l_i[i] = 0.f;
#pragma unroll
        for (int j = 0; j < 4; j++) o[i][j] = 0.f;
    }

    int kt0, kt1;
    if (is_local) { kt0 = (qt > 0) ? (qt - 1) : 0; kt1 = qt; }
    else          { kt0 = 0; kt1 = NQT - 1; }

    for (int kt = kt0; kt <= kt1; kt++) {
        __syncthreads();
        int k0 = kt * 64;
#pragma unroll
        for (int i = 0; i < 4; i++) {
            int linear = tid + i * 256;
            int r = linear >> 4;
            int d = (linear & 15) * 4;
            const float* krow = base + (size_t)(k0 + r) * QKVD;
            float4 k4 = *(const float4*)(krow + koff + d);
            Kst[(d + 0) * FA_STRIDE + r] = k4.x;
            Kst[(d + 1) * FA_STRIDE + r] = k4.y;
            Kst[(d + 2) * FA_STRIDE + r] = k4.z;
            Kst[(d + 3) * FA_STRIDE + r] = k4.w;
            float4 v4 = *(const float4*)(krow + voff + d);
            *(float4*)&Vs[r * 64 + d] = v4;
        }
        __syncthreads();

        float s[4][4];
#pragma unroll
        for (int i = 0; i < 4; i++)
#pragma unroll
            for (int j = 0; j < 4; j++) s[i][j] = 0.f;

#pragma unroll 4
        for (int k = 0; k < 64; k++) {
            float qv[4], kv[4];
#pragma unroll
            for (int i = 0; i < 4; i++) qv[i] = Qst[k * FA_STRIDE + ty * 4 + i];
#pragma unroll
            for (int j = 0; j < 4; j++) kv[j] = Kst[k * FA_STRIDE + tx * 4 + j];
#pragma unroll
            for (int i = 0; i < 4; i++)
#pragma unroll
                for (int j = 0; j < 4; j++)
                    s[i][j] += qv[i] * kv[j];
        }

#pragma unroll
        for (int i = 0; i < 4; i++) {
            float sc0 = s[i][0] * ATT_SCALE, sc1 = s[i][1] * ATT_SCALE;
            float sc2 = s[i][2] * ATT_SCALE, sc3 = s[i][3] * ATT_SCALE;
            float rm = fmaxf(fmaxf(sc0, sc1), fmaxf(sc2, sc3));
#pragma unroll
            for (int off = 8; off > 0; off >>= 1)
                rm = fmaxf(rm, __shfl_xor_sync(0xffffffffu, rm, off));
            float mnew = fmaxf(m_i[i], rm);
            float corr = __expf(m_i[i] - mnew);
            m_i[i] = mnew;
            float p0 = __expf(sc0 - mnew);
            float p1 = __expf(sc1 - mnew);
            float p2 = __expf(sc2 - mnew);
            float p3 = __expf(sc3 - mnew);
            s[i][0] = p0; s[i][1] = p1; s[i][2] = p2; s[i][3] = p3;
            float rs = p0 + p1 + p2 + p3;
#pragma unroll
            for (int off = 8; off > 0; off >>= 1)
                rs += __shfl_xor_sync(0xffffffffu, rs, off);
            l_i[i] = l_i[i] * corr + rs;
#pragma unroll
            for (int j = 0; j < 4; j++) o[i][j] *= corr;
        }

        __syncthreads();
#pragma unroll
        for (int i = 0; i < 4; i++)
#pragma unroll
            for (int j = 0; j < 4; j++)
                Kst[(ty * 4 + i) * FA_STRIDE + tx * 4 + j] = s[i][j];
        __syncthreads();

#pragma unroll 4
        for (int c = 0; c < 64; c++) {
            float4 v4 = *(const float4*)&Vs[c * 64 + tx * 4];
            float pr[4];
#pragma unroll
            for (int i = 0; i < 4; i++) pr[i] = Kst[(ty * 4 + i) * FA_STRIDE + c];
#pragma unroll
            for (int i = 0; i < 4; i++) {
                o[i][0] += pr[i] * v4.x;
                o[i][1] += pr[i] * v4.y;
                o[i][2] += pr[i] * v4.z;
                o[i][3] += pr[i] * v4.w;
            }
        }
    }

    int colofs = is_local ? 0 : DMODEL;
#pragma unroll
    for (int i = 0; i < 4; i++) {
        float inv = 1.f / l_i[i];
        int r = q0 + ty * 4 + i;
        size_t dbase = (size_t)(b * SLEN + r) * KCAT + colofs + h * DHEAD + tx * 4;
        float val[4];
#pragma unroll
        for (int j = 0; j < 4; j++) val[j] = o[i][j] * inv;
        __nv_bfloat162 h0, h1, l0, l1;
        h0.x = __float2bfloat16(val[0]); h0.y = __float2bfloat16(val[1]);
        h1.x = __float2bfloat16(val[2]); h1.y = __float2bfloat16(val[3]);
        l0.x = __float2bfloat16(val[0] - __bfloat162float(h0.x));
        l0.y = __float2bfloat16(val[1] - __bfloat162float(h0.y));
        l1.x = __float2bfloat16(val[2] - __bfloat162float(h1.x));
        l1.y = __float2bfloat16(val[3] - __bfloat162float(h1.y));
        *(__nv_bfloat162*)&aoh[dbase]     = h0;
        *(__nv_bfloat162*)&aoh[dbase + 2] = h1;
        *(__nv_bfloat162*)&aol[dbase]     = l0;
        *(__nv_bfloat162*)&aol[dbase + 2] = l1;
    }
}

// ============================================================
// host launcher
// ============================================================
extern "C" void kernel_launch(void* const* d_in, const int* in_sizes, int n_in,
                              void* d_out, int out_size)
{
    const float* x      = (const float*)d_in[0];
    const float* ln_l_g = (const float*)d_in[1];
    const float* ln_l_b = (const float*)d_in[2];
    const float* Wqkv_l = (const float*)d_in[3];
    const float* bqkv_l = (const float*)d_in[4];
    const float* Wo_l   = (const float*)d_in[5];
    const float* bo_l   = (const float*)d_in[6];
    const float* ln_g_g = (const float*)d_in[7];
    const float* ln_g_b = (const float*)d_in[8];
    const float* Wqkv_g = (const float*)d_in[9];
    const float* bqkv_g = (const float*)d_in[10];
    const float* Wo_g   = (const float*)d_in[11];
    const float* bo_g   = (const float*)d_in[12];
    float* out = (float*)d_out;

    __nv_bfloat16 *xlh, *xll, *xgh, *xgl, *wqlh, *wqll, *wqgh, *wqgl, *woh, *wol, *aoh, *aol;
    float *qkv_l, *qkv_g;
    cudaGetSymbolAddress((void**)&xlh, g_xlh);
    cudaGetSymbolAddress((void**)&xll, g_xll);
    cudaGetSymbolAddress((void**)&xgh, g_xgh);
    cudaGetSymbolAddress((void**)&xgl, g_xgl);
    cudaGetSymbolAddress((void**)&qkv_l, g_qkv_l);
    cudaGetSymbolAddress((void**)&qkv_g, g_qkv_g);
    cudaGetSymbolAddress((void**)&wqlh, g_wqkvl_h);
    cudaGetSymbolAddress((void**)&wqll, g_wqkvl_l);
    cudaGetSymbolAddress((void**)&wqgh, g_wqkvg_h);
    cudaGetSymbolAddress((void**)&wqgl, g_wqkvg_l);
    cudaGetSymbolAddress((void**)&woh, g_wo_h);
    cudaGetSymbolAddress((void**)&wol, g_wo_l);
    cudaGetSymbolAddress((void**)&aoh, g_aoh);
    cudaGetSymbolAddress((void**)&aol, g_aol);

    cudaFuncSetAttribute(flash_kernel, cudaFuncAttributeMaxDynamicSharedMemorySize, FA_SMEM_BYTES);
    cudaFuncSetAttribute(gemm3bf16, cudaFuncAttributeMaxDynamicSharedMemorySize, GEMM_SMEM);

    // 1) dual LN -> bf16 hi/lo
    ln_dual_kernel<<<NROWS, 256>>>(x, ln_l_g, ln_l_b, ln_g_g, ln_g_b, xlh, xll, xgh, xgl);

    // 2) weight splits
    {
        int t4 = QKVD * DMODEL / 4;
        convert_split<<<(t4 + 255) / 256, 256>>>(Wqkv_l, wqlh, wqll, DMODEL / 4, DMODEL, 0, t4);
        convert_split<<<(t4 + 255) / 256, 256>>>(Wqkv_g, wqgh, wqgl, DMODEL / 4, DMODEL, 0, t4);
        int t4o = DMODEL * DMODEL / 4;
        convert_split<<<(t4o + 255) / 256, 256>>>(Wo_l, woh, wol, DMODEL / 4, KCAT, 0, t4o);
        convert_split<<<(t4o + 255) / 256, 256>>>(Wo_g, woh, wol, DMODEL / 4, KCAT, DMODEL, t4o);
    }

    // 3) QKV projections (HMMA split GEMM, pipelined)
    {
        dim3 g(QKVD / GBN, NROWS / GBM);
        gemm3bf16<<<g, 256, GEMM_SMEM>>>(xlh, xll, wqlh, wqll, bqkv_l, nullptr, qkv_l, QKVD, DMODEL);
        gemm3bf16<<<g, 256, GEMM_SMEM>>>(xgh, xgl, wqgh, wqgl, bqkv_g, nullptr, qkv_g, QKVD, DMODEL);
    }

    // 4) attention -> bf16 hi/lo into concatenated activation
    {
        dim3 gf(NQT, NHEAD, BATCH);
        flash_kernel<<<gf, 256, FA_SMEM_BYTES>>>(qkv_l, aoh, aol, 1);
        flash_kernel<<<gf, 256, FA_SMEM_BYTES>>>(qkv_g, aoh, aol, 0);
    }

    // 5) fused out-projection: [ao_l|ao_g] x [Wo_l|Wo_g]^T + bo_l + bo_g
    {
        dim3 g(DMODEL / GBN, NROWS / GBM);
        gemm3bf16<<<g, 256, GEMM_SMEM>>>(aoh, aol, woh, wol, bo_l, bo_g, out, DMODEL, KCAT);
    }
}

// round 7
// speedup vs baseline: 1.9296x; 1.2579x over previous
#include <cuda_runtime.h>
#include <cuda_fp16.h>
#include <math.h>
#include <stdint.h>

// ---------------- problem constants ----------------
#define BATCH   2
#define SLEN    2048
#define DMODEL  1024
#define NHEAD   16
#define DHEAD   64
#define NROWS   (BATCH * SLEN)          // 4096
#define QKVD    (3 * DMODEL)            // 3072
#define KCAT    (2 * DMODEL)            // 2048
#define NQT     (SLEN / 64)             // 32
#define ATT_SCALE 0.125f

// ---------------- scratch (device globals) ----------------
__device__ __align__(16) __half g_xlf[NROWS * DMODEL];          // LN local, fp16
__device__ __align__(16) __half g_xgf[NROWS * DMODEL];          // LN global, fp16
__device__ __align__(16) float  g_qkv_l[(size_t)NROWS * QKVD];
__device__ __align__(16) float  g_qkv_g[(size_t)NROWS * QKVD];
__device__ __align__(16) __half g_wqkvl_f[QKVD * DMODEL];       // fp16 hi only
__device__ __align__(16) __half g_wqkvg_f[QKVD * DMODEL];
__device__ __align__(16) __half g_wo_h[DMODEL * KCAT];          // cat(Wo_l,Wo_g), fp16 hi
__device__ __align__(16) __half g_wo_l[DMODEL * KCAT];          // fp16 lo residual
__device__ __align__(16) __half g_aoh[(size_t)NROWS * KCAT];    // cat(ao_l,ao_g), fp16 hi
__device__ __align__(16) __half g_aol[(size_t)NROWS * KCAT];    // fp16 lo residual

__device__ __forceinline__ uint32_t smem_u32(const void* p) {
    uint32_t a;
    asm("{ .reg .u64 t; cvta.to.shared.u64 t, %1; cvt.u32.u64 %0, t; }" : "=r"(a) : "l"(p));
    return a;
}

// ============================================================
// Kernel 1: fused dual LayerNorm -> fp16 for both branches
// ============================================================
__global__ __launch_bounds__(256) void ln_dual_kernel(
    const float* __restrict__ x,
    const float* __restrict__ gl, const float* __restrict__ bl,
    const float* __restrict__ gg, const float* __restrict__ bg,
    __half* __restrict__ xl, __half* __restrict__ xg)
{
    int row = blockIdx.x;
    const float* xr = x + (size_t)row * DMODEL;
    int t = threadIdx.x;

    float v[4];
    float s = 0.f, s2 = 0.f;
#pragma unroll
    for (int i = 0; i < 4; i++) {
        float a = xr[t + i * 256];
        v[i] = a; s += a; s2 += a * a;
    }
#pragma unroll
    for (int o = 16; o > 0; o >>= 1) {
        s  += __shfl_xor_sync(0xffffffffu, s,  o);
        s2 += __shfl_xor_sync(0xffffffffu, s2, o);
    }
    __shared__ float red0[8], red1[8], stat[2];
    int warp = t >> 5, lane = t & 31;
    if (lane == 0) { red0[warp] = s; red1[warp] = s2; }
    __syncthreads();
    if (t < 32) {
        float a = (t < 8) ? red0[t] : 0.f;
        float b = (t < 8) ? red1[t] : 0.f;
#pragma unroll
        for (int o = 4; o > 0; o >>= 1) {
            a += __shfl_xor_sync(0xffffffffu, a, o);
            b += __shfl_xor_sync(0xffffffffu, b, o);
        }
        if (t == 0) {
            float mean = a * (1.f / DMODEL);
            float var  = b * (1.f / DMODEL) - mean * mean;
            stat[0] = mean;
            stat[1] = rsqrtf(var + 1e-5f);
        }
    }
    __syncthreads();
    float mean = stat[0], rstd = stat[1];
    size_t rb = (size_t)row * DMODEL;
#pragma unroll
    for (int i = 0; i < 4; i++) {
        int c = t + i * 256;
        float n = (v[i] - mean) * rstd;
        xl[rb + c] = __float2half(n * gl[c] + bl[c]);
        xg[rb + c] = __float2half(n * gg[c] + bg[c]);
    }
}

// ============================================================
// Kernel 2: weight convert fp32 -> fp16 hi (+ optional lo residual),
// remapped destination (dst elem = r*dstride + doff + c).
// ============================================================
__global__ __launch_bounds__(256) void convert_f16(
    const float* __restrict__ src, __half* __restrict__ h,
    __half* __restrict__ l, int cols4, int dstride, int doff, int total4)
{
    int idx = blockIdx.x * 256 + threadIdx.x;
    if (idx >= total4) return;
    int r = idx / cols4;
    int c4 = idx - r * cols4;
    float4 v = ((const float4*)src)[idx];
    size_t d = (size_t)r * dstride + doff + c4 * 4;
    float vv[4] = {v.x, v.y, v.z, v.w};
#pragma unroll
    for (int j = 0; j < 4; j++) {
        __half hi = __float2half(vv[j]);
        h[d + j] = hi;
        if (l) l[d + j] = __float2half(vv[j] - __half2float(hi));
    }
}

// ============================================================
// Kernel 3: fp16 GEMM via mma.sync.m16n8k16 (HMMA)
//   three_pass=0: C = Ah Bh^T (single pass)
//   three_pass=1: virtual K=3K phases AhBh, AhBl, AlBh (22-bit split)
//   CTA 128x128, BK=64, 3-stage cp.async ring, XOR-swizzled smem.
// ============================================================
#define GBM 128
#define GBN 128
#define TILE_SB  16384                 // 128 rows x 128B
#define STAGE_SB 32768                 // A + B
#define NSTAGE   3
#define GEMM_SMEM (NSTAGE * STAGE_SB)  // 98304

#define LDSM_X4(r0, r1, r2, r3, a) \
    asm volatile("ldmatrix.sync.aligned.m8n8.x4.shared.b16 {%0,%1,%2,%3}, [%4];" \
                 : "=r"(r0), "=r"(r1), "=r"(r2), "=r"(r3) : "r"(a))

#define MMA16816(c, a, b) \
    asm volatile("mma.sync.aligned.m16n8k16.row.col.f32.f16.f16.f32 " \
                 "{%0,%1,%2,%3}, {%4,%5,%6,%7}, {%8,%9}, {%0,%1,%2,%3};" \
                 : "+f"((c)[0]), "+f"((c)[1]), "+f"((c)[2]), "+f"((c)[3]) \
                 : "r"((a)[0]), "r"((a)[1]), "r"((a)[2]), "r"((a)[3]), \
                   "r"((b)[0]), "r"((b)[1]))

#define CP_ASYNC16(s, g) \
    asm volatile("cp.async.cg.shared.global [%0], [%1], 16;" :: "r"(s), "l"(g))
#define CP_COMMIT() asm volatile("cp.async.commit_group;")
#define CP_WAIT1()  asm volatile("cp.async.wait_group 1;")

__global__ __launch_bounds__(256, 2) void gemm_f16(
    const __half* __restrict__ Ah, const __half* __restrict__ Al,
    const __half* __restrict__ Bh, const __half* __restrict__ Bl,
    const float* __restrict__ bias0, const float* __restrict__ bias1,
    float* __restrict__ C, int Ntotal, int K, int three_pass)
{
    extern __shared__ char gsm[];
    uint32_t sbase = smem_u32(gsm);

    int tid = threadIdx.x;
    int m0 = blockIdx.y * GBM;
    int n0 = blockIdx.x * GBN;
    int lane = tid & 31;
    int wid = tid >> 5;
    int warp_m = (wid >> 2) * 64;
    int warp_n = (wid & 3) * 32;

    int kslabs = K >> 6;
    int nslab = three_pass ? 3 * kslabs : kslabs;

    // loader geometry: 4 chunks of 16B per tile per thread
    int l_row = tid >> 1;                   // 0..127
    int l_c0  = (tid & 1) * 4;              // 0 or 4
    int l_sw  = l_row & 7;
    uint32_t l_sm_base = (uint32_t)(l_row * 128);

    float acc[4][4][4];
#pragma unroll
    for (int i = 0; i < 4; i++)
#pragma unroll
        for (int j = 0; j < 4; j++)
#pragma unroll
            for (int q = 0; q < 4; q++) acc[i][j][q] = 0.f;

    // ldmatrix geometry (swizzled): addr = rowbase + ((chunk ^ (row&7))<<4)
    uint32_t a_rb[4]; int a_rs[4];
#pragma unroll
    for (int i = 0; i < 4; i++) {
        int r = warp_m + 16 * i + (lane & 15);
        a_rb[i] = (uint32_t)(r * 128);
        a_rs[i] = r & 7;
    }
    uint32_t b_rb[2]; int b_rs[2];
#pragma unroll
    for (int j = 0; j < 2; j++) {
        int r = warp_n + 16 * j + (lane & 7) + ((lane & 16) >> 1);
        b_rb[j] = (uint32_t)(r * 128);
        b_rs[j] = r & 7;
    }
    int cA0 = (lane >> 4);          // 0..1
    int cB0 = ((lane >> 3) & 1);    // 0..1

    auto load_slab = [&](int s, int buf) {
        const __half* As;
        const __half* Bs;
        int ks;
        if (s < kslabs)          { As = Ah; Bs = Bh; ks = s << 6; }
        else if (s < 2 * kslabs) { As = Ah; Bs = Bl; ks = (s - kslabs) << 6; }
        else                     { As = Al; Bs = Bh; ks = (s - 2 * kslabs) << 6; }
        uint32_t sa = sbase + buf * STAGE_SB + l_sm_base;
        uint32_t sb = sa + TILE_SB;
        const __half* ga = As + (size_t)(m0 + l_row) * K + ks + l_c0 * 8;
        const __half* gb = Bs + (size_t)(n0 + l_row) * K + ks + l_c0 * 8;
#pragma unroll
        for (int q = 0; q < 4; q++) {
            int phys = ((l_c0 + q) ^ l_sw) << 4;
            CP_ASYNC16(sa + phys, ga + q * 8);
        }
#pragma unroll
        for (int q = 0; q < 4; q++) {
            int phys = ((l_c0 + q) ^ l_sw) << 4;
            CP_ASYNC16(sb + phys, gb + q * 8);
        }
    };

    load_slab(0, 0); CP_COMMIT();
    load_slab(1, 1); CP_COMMIT();

    int buf = 0;       // = s % 3
    int pbuf = 2;      // = (s+2) % 3
    for (int s = 0; s < nslab; s++) {
        CP_WAIT1();            // stage s complete (≤1 group pending)
        __syncthreads();       // all warps done with stage s-1; pbuf free

        if (s + 2 < nslab) load_slab(s + 2, pbuf);
        CP_COMMIT();

        uint32_t sa = sbase + buf * STAGE_SB;
        uint32_t sb = sa + TILE_SB;
#pragma unroll
        for (int kk = 0; kk < 4; kk++) {
            uint32_t a[4][4];
#pragma unroll
            for (int i = 0; i < 4; i++) {
                uint32_t ad = sa + a_rb[i] + (uint32_t)((((cA0 + 2 * kk) ^ a_rs[i])) << 4);
                LDSM_X4(a[i][0], a[i][1], a[i][2], a[i][3], ad);
            }
            uint32_t b[4][2];
#pragma unroll
            for (int j = 0; j < 2; j++) {
                uint32_t bd = sb + b_rb[j] + (uint32_t)((((cB0 + 2 * kk) ^ b_rs[j])) << 4);
                uint32_t t0, t1, t2, t3;
                LDSM_X4(t0, t1, t2, t3, bd);
                b[2 * j][0] = t0; b[2 * j][1] = t1;
                b[2 * j + 1][0] = t2; b[2 * j + 1][1] = t3;
            }
#pragma unroll
            for (int i = 0; i < 4; i++)
#pragma unroll
                for (int j = 0; j < 4; j++)
                    MMA16816(acc[i][j], a[i], b[j]);
        }

        buf = (buf == 2) ? 0 : buf + 1;
        pbuf = (pbuf == 2) ? 0 : pbuf + 1;
    }

    // ---- epilogue ----
#pragma unroll
    for (int i = 0; i < 4; i++) {
        int r0 = m0 + warp_m + 16 * i + (lane >> 2);
#pragma unroll
        for (int j = 0; j < 4; j++) {
            int col = n0 + warp_n + 8 * j + (lane & 3) * 2;
            float b0v = bias0[col], b1v = bias0[col + 1];
            if (bias1) { b0v += bias1[col]; b1v += bias1[col + 1]; }
            float2* p0 = (float2*)(C + (size_t)r0 * Ntotal + col);
            float2* p1 = (float2*)(C + (size_t)(r0 + 8) * Ntotal + col);
            float2 v0; v0.x = acc[i][j][0] + b0v; v0.y = acc[i][j][1] + b1v;
            float2 v1; v1.x = acc[i][j][2] + b0v; v1.y = acc[i][j][3] + b1v;
            *p0 = v0;
            *p1 = v1;
        }
    }
}

// ============================================================
// Kernel 4: flash attention (fp32); writes fp16 hi/lo into cat'd ao buffer.
// ============================================================
#define FA_STRIDE 65
#define FA_SMEM_BYTES ((64 * FA_STRIDE * 2 + 64 * 64) * 4)

__global__ __launch_bounds__(256) void flash_kernel(
    const float* __restrict__ qkv,
    __half* __restrict__ aoh, __half* __restrict__ aol,
    int is_local)
{
    extern __shared__ float sm[];
    float* Qst = sm;
    float* Kst = sm + 64 * FA_STRIDE;
    float* Vs  = sm + 2 * 64 * FA_STRIDE;

    int qt = blockIdx.x;
    int h  = blockIdx.y;
    int b  = blockIdx.z;
    int q0 = qt * 64;

    const float* base = qkv + (size_t)b * SLEN * QKVD;
    int qoff = h * DHEAD;
    int koff = DMODEL + h * DHEAD;
    int voff = 2 * DMODEL + h * DHEAD;

    int tid = threadIdx.x;
    int ty = tid >> 4;
    int tx = tid & 15;

#pragma unroll
    for (int i = 0; i < 4; i++) {
        int linear = tid + i * 256;
        int r = linear >> 4;
        int d = (linear & 15) * 4;
        float4 q4 = *(const float4*)(base + (size_t)(q0 + r) * QKVD + qoff + d);
        Qst[(d + 0) * FA_STRIDE + r] = q4.x;
        Qst[(d + 1) * FA_STRIDE + r] = q4.y;
        Qst[(d + 2) * FA_STRIDE + r] = q4.z;
        Qst[(d + 3) * FA_STRIDE + r] = q4.w;
    }

    float m_i[4], l_i[4], o[4][4];
#pragma unroll
    for (int i = 0; i < 4; i++) {
        m_i[i] = -1e30f; l_i[i] = 0.f;
#pragma unroll
        for (int j = 0; j < 4; j++) o[i][j] = 0.f;
    }

    int kt0, kt1;
    if (is_local) { kt0 = (qt > 0) ? (qt - 1) : 0; kt1 = qt; }
    else          { kt0 = 0; kt1 = NQT - 1; }

    for (int kt = kt0; kt <= kt1; kt++) {
        __syncthreads();
        int k0 = kt * 64;
#pragma unroll
        for (int i = 0; i < 4; i++) {
            int linear = tid + i * 256;
            int r = linear >> 4;
            int d = (linear & 15) * 4;
            const float* krow = base + (size_t)(k0 + r) * QKVD;
            float4 k4 = *(const float4*)(krow + koff + d);
            Kst[(d + 0) * FA_STRIDE + r] = k4.x;
            Kst[(d + 1) * FA_STRIDE + r] = k4.y;
            Kst[(d + 2) * FA_STRIDE + r] = k4.z;
            Kst[(d + 3) * FA_STRIDE + r] = k4.w;
            float4 v4 = *(const float4*)(krow + voff + d);
            *(float4*)&Vs[r * 64 + d] = v4;
        }
        __syncthreads();

        float s[4][4];
#pragma unroll
        for (int i = 0; i < 4; i++)
#pragma unroll
            for (int j = 0; j < 4; j++) s[i][j] = 0.f;

#pragma unroll 4
        for (int k = 0; k < 64; k++) {
            float qv[4], kv[4];
#pragma unroll
            for (int i = 0; i < 4; i++) qv[i] = Qst[k * FA_STRIDE + ty * 4 + i];
#pragma unroll
            for (int j = 0; j < 4; j++) kv[j] = Kst[k * FA_STRIDE + tx * 4 + j];
#pragma unroll
            for (int i = 0; i < 4; i++)
#pragma unroll
                for (int j = 0; j < 4; j++)
                    s[i][j] += qv[i] * kv[j];
        }

#pragma unroll
        for (int i = 0; i < 4; i++) {
            float sc0 = s[i][0] * ATT_SCALE, sc1 = s[i][1] * ATT_SCALE;
            float sc2 = s[i][2] * ATT_SCALE, sc3 = s[i][3] * ATT_SCALE;
            float rm = fmaxf(fmaxf(sc0, sc1), fmaxf(sc2, sc3));
#pragma unroll
            for (int off = 8; off > 0; off >>= 1)
                rm = fmaxf(rm, __shfl_xor_sync(0xffffffffu, rm, off));
            float mnew = fmaxf(m_i[i], rm);
            float corr = __expf(m_i[i] - mnew);
            m_i[i] = mnew;
            float p0 = __expf(sc0 - mnew);
            float p1 = __expf(sc1 - mnew);
            float p2 = __expf(sc2 - mnew);
            float p3 = __expf(sc3 - mnew);
            s[i][0] = p0; s[i][1] = p1; s[i][2] = p2; s[i][3] = p3;
            float rs = p0 + p1 + p2 + p3;
#pragma unroll
            for (int off = 8; off > 0; off >>= 1)
                rs += __shfl_xor_sync(0xffffffffu, rs, off);
            l_i[i] = l_i[i] * corr + rs;
#pragma unroll
            for (int j = 0; j < 4; j++) o[i][j] *= corr;
        }

        __syncthreads();
#pragma unroll
        for (int i = 0; i < 4; i++)
#pragma unroll
            for (int j = 0; j < 4; j++)
                Kst[(ty * 4 + i) * FA_STRIDE + tx * 4 + j] = s[i][j];
        __syncthreads();

#pragma unroll 4
        for (int c = 0; c < 64; c++) {
            float4 v4 = *(const float4*)&Vs[c * 64 + tx * 4];
            float pr[4];
#pragma unroll
            for (int i = 0; i < 4; i++) pr[i] = Kst[(ty * 4 + i) * FA_STRIDE + c];
#pragma unroll
            for (int i = 0; i < 4; i++) {
                o[i][0] += pr[i] * v4.x;
                o[i][1] += pr[i] * v4.y;
                o[i][2] += pr[i] * v4.z;
                o[i][3] += pr[i] * v4.w;
            }
        }
    }

    int colofs = is_local ? 0 : DMODEL;
#pragma unroll
    for (int i = 0; i < 4; i++) {
        float inv = 1.f / l_i[i];
        int r = q0 + ty * 4 + i;
        size_t dbase = (size_t)(b * SLEN + r) * KCAT + colofs + h * DHEAD + tx * 4;
        float val[4];
#pragma unroll
        for (int j = 0; j < 4; j++) val[j] = o[i][j] * inv;
        __half2 h0, h1, l0, l1;
        h0.x = __float2half(val[0]); h0.y = __float2half(val[1]);
        h1.x = __float2half(val[2]); h1.y = __float2half(val[3]);
        l0.x = __float2half(val[0] - __half2float(h0.x));
        l0.y = __float2half(val[1] - __half2float(h0.y));
        l1.x = __float2half(val[2] - __half2float(h1.x));
        l1.y = __float2half(val[3] - __half2float(h1.y));
        *(__half2*)&aoh[dbase]     = h0;
        *(__half2*)&aoh[dbase + 2] = h1;
        *(__half2*)&aol[dbase]     = l0;
        *(__half2*)&aol[dbase + 2] = l1;
    }
}

// ============================================================
// host launcher
// ============================================================
extern "C" void kernel_launch(void* const* d_in, const int* in_sizes, int n_in,
                              void* d_out, int out_size)
{
    const float* x      = (const float*)d_in[0];
    const float* ln_l_g = (const float*)d_in[1];
    const float* ln_l_b = (const float*)d_in[2];
    const float* Wqkv_l = (const float*)d_in[3];
    const float* bqkv_l = (const float*)d_in[4];
    const float* Wo_l   = (const float*)d_in[5];
    const float* bo_l   = (const float*)d_in[6];
    const float* ln_g_g = (const float*)d_in[7];
    const float* ln_g_b = (const float*)d_in[8];
    const float* Wqkv_g = (const float*)d_in[9];
    const float* bqkv_g = (const float*)d_in[10];
    const float* Wo_g   = (const float*)d_in[11];
    const float* bo_g   = (const float*)d_in[12];
    float* out = (float*)d_out;

    __half *xlf, *xgf, *wqlf, *wqgf, *woh, *wol, *aoh, *aol;
    float *qkv_l, *qkv_g;
    cudaGetSymbolAddress((void**)&xlf, g_xlf);
    cudaGetSymbolAddress((void**)&xgf, g_xgf);
    cudaGetSymbolAddress((void**)&qkv_l, g_qkv_l);
    cudaGetSymbolAddress((void**)&qkv_g, g_qkv_g);
    cudaGetSymbolAddress((void**)&wqlf, g_wqkvl_f);
    cudaGetSymbolAddress((void**)&wqgf, g_wqkvg_f);
    cudaGetSymbolAddress((void**)&woh, g_wo_h);
    cudaGetSymbolAddress((void**)&wol, g_wo_l);
    cudaGetSymbolAddress((void**)&aoh, g_aoh);
    cudaGetSymbolAddress((void**)&aol, g_aol);

    cudaFuncSetAttribute(flash_kernel, cudaFuncAttributeMaxDynamicSharedMemorySize, FA_SMEM_BYTES);
    cudaFuncSetAttribute(gemm_f16, cudaFuncAttributeMaxDynamicSharedMemorySize, GEMM_SMEM);

    // 1) dual LN -> fp16
    ln_dual_kernel<<<NROWS, 256>>>(x, ln_l_g, ln_l_b, ln_g_g, ln_g_b, xlf, xgf);

    // 2) weight converts (QKV: hi only; Wo: hi/lo into cat layout)
    {
        int t4 = QKVD * DMODEL / 4;
        convert_f16<<<(t4 + 255) / 256, 256>>>(Wqkv_l, wqlf, nullptr, DMODEL / 4, DMODEL, 0, t4);
        convert_f16<<<(t4 + 255) / 256, 256>>>(Wqkv_g, wqgf, nullptr, DMODEL / 4, DMODEL, 0, t4);
        int t4o = DMODEL * DMODEL / 4;
        convert_f16<<<(t4o + 255) / 256, 256>>>(Wo_l, woh, wol, DMODEL / 4, KCAT, 0, t4o);
        convert_f16<<<(t4o + 255) / 256, 256>>>(Wo_g, woh, wol, DMODEL / 4, KCAT, DMODEL, t4o);
    }

    // 3) QKV projections: single-pass fp16
    {
        dim3 g(QKVD / GBN, NROWS / GBM);
        gemm_f16<<<g, 256, GEMM_SMEM>>>(xlf, nullptr, wqlf, nullptr, bqkv_l, nullptr,
                                        qkv_l, QKVD, DMODEL, 0);
        gemm_f16<<<g, 256, GEMM_SMEM>>>(xgf, nullptr, wqgf, nullptr, bqkv_g, nullptr,
                                        qkv_g, QKVD, DMODEL, 0);
    }

    // 4) attention -> fp16 hi/lo into concatenated activation
    {
        dim3 gf(NQT, NHEAD, BATCH);
        flash_kernel<<<gf, 256, FA_SMEM_BYTES>>>(qkv_l, aoh, aol, 1);
        flash_kernel<<<gf, 256, FA_SMEM_BYTES>>>(qkv_g, aoh, aol, 0);
    }

    // 5) fused out-projection (exact 3-pass fp16 split): cat(ao) x cat(Wo)^T + biases
    {
        dim3 g(DMODEL / GBN, NROWS / GBM);
        gemm_f16<<<g, 256, GEMM_SMEM>>>(aoh, aol, woh, wol, bo_l, bo_g, out, DMODEL, KCAT, 1);
    }
}

// round 8
// speedup vs baseline: 2.1562x; 1.1174x over previous
#include <cuda_runtime.h>
#include <cuda_fp16.h>
#include <math.h>
#include <stdint.h>

// ---------------- problem constants ----------------
#define BATCH   2
#define SLEN    2048
#define DMODEL  1024
#define NHEAD   16
#define DHEAD   64
#define NROWS   (BATCH * SLEN)          // 4096
#define QKVD    (3 * DMODEL)            // 3072
#define KCAT    (2 * DMODEL)            // 2048
#define NQT     (SLEN / 64)             // 32
#define ATT_SCALE 0.125f

// ---------------- scratch (device globals) ----------------
__device__ __align__(16) __half g_xlf[NROWS * DMODEL];          // LN local, fp16
__device__ __align__(16) __half g_xgf[NROWS * DMODEL];          // LN global, fp16
__device__ __align__(16) float  g_qkv_l[(size_t)NROWS * QKVD];
__device__ __align__(16) float  g_qkv_g[(size_t)NROWS * QKVD];
__device__ __align__(16) __half g_wqkvl_f[QKVD * DMODEL];
__device__ __align__(16) __half g_wqkvg_f[QKVD * DMODEL];
__device__ __align__(16) __half g_wo_f[DMODEL * KCAT];          // cat(Wo_l,Wo_g) along K
__device__ __align__(16) __half g_aof[(size_t)NROWS * KCAT];    // cat(ao_l,ao_g)

__device__ __forceinline__ uint32_t smem_u32(const void* p) {
    uint32_t a;
    asm("{ .reg .u64 t; cvta.to.shared.u64 t, %1; cvt.u32.u64 %0, t; }" : "=r"(a) : "l"(p));
    return a;
}

// ============================================================
// Kernel 1: fused dual LayerNorm -> fp16 for both branches
// ============================================================
__global__ __launch_bounds__(256) void ln_dual_kernel(
    const float* __restrict__ x,
    const float* __restrict__ gl, const float* __restrict__ bl,
    const float* __restrict__ gg, const float* __restrict__ bg,
    __half* __restrict__ xl, __half* __restrict__ xg)
{
    int row = blockIdx.x;
    const float* xr = x + (size_t)row * DMODEL;
    int t = threadIdx.x;

    float v[4];
    float s = 0.f, s2 = 0.f;
#pragma unroll
    for (int i = 0; i < 4; i++) {
        float a = xr[t + i * 256];
        v[i] = a; s += a; s2 += a * a;
    }
#pragma unroll
    for (int o = 16; o > 0; o >>= 1) {
        s  += __shfl_xor_sync(0xffffffffu, s,  o);
        s2 += __shfl_xor_sync(0xffffffffu, s2, o);
    }
    __shared__ float red0[8], red1[8], stat[2];
    int warp = t >> 5, lane = t & 31;
    if (lane == 0) { red0[warp] = s; red1[warp] = s2; }
    __syncthreads();
    if (t < 32) {
        float a = (t < 8) ? red0[t] : 0.f;
        float b = (t < 8) ? red1[t] : 0.f;
#pragma unroll
        for (int o = 4; o > 0; o >>= 1) {
            a += __shfl_xor_sync(0xffffffffu, a, o);
            b += __shfl_xor_sync(0xffffffffu, b, o);
        }
        if (t == 0) {
            float mean = a * (1.f / DMODEL);
            float var  = b * (1.f / DMODEL) - mean * mean;
            stat[0] = mean;
            stat[1] = rsqrtf(var + 1e-5f);
        }
    }
    __syncthreads();
    float mean = stat[0], rstd = stat[1];
    size_t rb = (size_t)row * DMODEL;
#pragma unroll
    for (int i = 0; i < 4; i++) {
        int c = t + i * 256;
        float n = (v[i] - mean) * rstd;
        xl[rb + c] = __float2half(n * gl[c] + bl[c]);
        xg[rb + c] = __float2half(n * gg[c] + bg[c]);
    }
}

// ============================================================
// Kernel 2: weight convert fp32 -> fp16 (remapped destination)
// ============================================================
__global__ __launch_bounds__(256) void convert_f16(
    const float* __restrict__ src, __half* __restrict__ h,
    int cols4, int dstride, int doff, int total4)
{
    int idx = blockIdx.x * 256 + threadIdx.x;
    if (idx >= total4) return;
    int r = idx / cols4;
    int c4 = idx - r * cols4;
    float4 v = ((const float4*)src)[idx];
    size_t d = (size_t)r * dstride + doff + c4 * 4;
    __half2 h0, h1;
    h0.x = __float2half(v.x); h0.y = __float2half(v.y);
    h1.x = __float2half(v.z); h1.y = __float2half(v.w);
    *(__half2*)&h[d]     = h0;
    *(__half2*)&h[d + 2] = h1;
}

// ============================================================
// Kernel 3: fp16 single-pass GEMM via mma.sync.m16n8k16 (HMMA)
//   C = A B^T + bias0 (+bias1). CTA 128x128, BK=64, 3-stage cp.async ring,
//   XOR-swizzled smem, 8 warps of 64x32.
//   batch2: blockIdx.z selects (A2,B2,bias2,C2) for batched QKV launch.
// ============================================================
#define GBM 128
#define GBN 128
#define TILE_SB  16384
#define STAGE_SB 32768
#define NSTAGE   3
#define GEMM_SMEM (NSTAGE * STAGE_SB)  // 98304

#define LDSM_X4(r0, r1, r2, r3, a) \
    asm volatile("ldmatrix.sync.aligned.m8n8.x4.shared.b16 {%0,%1,%2,%3}, [%4];" \
                 : "=r"(r0), "=r"(r1), "=r"(r2), "=r"(r3) : "r"(a))

#define MMA16816(c, a, b) \
    asm volatile("mma.sync.aligned.m16n8k16.row.col.f32.f16.f16.f32 " \
                 "{%0,%1,%2,%3}, {%4,%5,%6,%7}, {%8,%9}, {%0,%1,%2,%3};" \
                 : "+f"((c)[0]), "+f"((c)[1]), "+f"((c)[2]), "+f"((c)[3]) \
                 : "r"((a)[0]), "r"((a)[1]), "r"((a)[2]), "r"((a)[3]), \
                   "r"((b)[0]), "r"((b)[1]))

#define CP_ASYNC16(s, g) \
    asm volatile("cp.async.cg.shared.global [%0], [%1], 16;" :: "r"(s), "l"(g))
#define CP_COMMIT() asm volatile("cp.async.commit_group;")
#define CP_WAIT1()  asm volatile("cp.async.wait_group 1;")

__global__ __launch_bounds__(256, 2) void gemm_f16(
    const __half* __restrict__ A0, const __half* __restrict__ B0,
    const float* __restrict__ bias0a, float* __restrict__ C0,
    const __half* __restrict__ A1, const __half* __restrict__ B1,
    const float* __restrict__ bias1a, float* __restrict__ C1,
    const float* __restrict__ biasExtra,   // added on top of selected bias (outproj dual bias)
    int Ntotal, int K)
{
    extern __shared__ char gsm[];
    uint32_t sbase = smem_u32(gsm);

    int tid = threadIdx.x;
    int m0 = blockIdx.y * GBM;
    int n0 = blockIdx.x * GBN;
    int lane = tid & 31;
    int wid = tid >> 5;
    int warp_m = (wid >> 2) * 64;
    int warp_n = (wid & 3) * 32;

    const __half* A = (blockIdx.z == 0) ? A0 : A1;
    const __half* B = (blockIdx.z == 0) ? B0 : B1;
    const float* bias = (blockIdx.z == 0) ? bias0a : bias1a;
    float* C = (blockIdx.z == 0) ? C0 : C1;

    int nslab = K >> 6;

    int l_row = tid >> 1;
    int l_c0  = (tid & 1) * 4;
    int l_sw  = l_row & 7;
    uint32_t l_sm_base = (uint32_t)(l_row * 128);

    float acc[4][4][4];
#pragma unroll
    for (int i = 0; i < 4; i++)
#pragma unroll
        for (int j = 0; j < 4; j++)
#pragma unroll
            for (int q = 0; q < 4; q++) acc[i][j][q] = 0.f;

    uint32_t a_rb[4]; int a_rs[4];
#pragma unroll
    for (int i = 0; i < 4; i++) {
        int r = warp_m + 16 * i + (lane & 15);
        a_rb[i] = (uint32_t)(r * 128);
        a_rs[i] = r & 7;
    }
    uint32_t b_rb[2]; int b_rs[2];
#pragma unroll
    for (int j = 0; j < 2; j++) {
        int r = warp_n + 16 * j + (lane & 7) + ((lane & 16) >> 1);
        b_rb[j] = (uint32_t)(r * 128);
        b_rs[j] = r & 7;
    }
    int cA0 = (lane >> 4);
    int cB0 = ((lane >> 3) & 1);

    auto load_slab = [&](int s, int buf) {
        int ks = s << 6;
        uint32_t sa = sbase + buf * STAGE_SB + l_sm_base;
        uint32_t sb = sa + TILE_SB;
        const __half* ga = A + (size_t)(m0 + l_row) * K + ks + l_c0 * 8;
        const __half* gb = B + (size_t)(n0 + l_row) * K + ks + l_c0 * 8;
#pragma unroll
        for (int q = 0; q < 4; q++) {
            int phys = ((l_c0 + q) ^ l_sw) << 4;
            CP_ASYNC16(sa + phys, ga + q * 8);
        }
#pragma unroll
        for (int q = 0; q < 4; q++) {
            int phys = ((l_c0 + q) ^ l_sw) << 4;
            CP_ASYNC16(sb + phys, gb + q * 8);
        }
    };

    load_slab(0, 0); CP_COMMIT();
    load_slab(1, 1); CP_COMMIT();

    int buf = 0, pbuf = 2;
    for (int s = 0; s < nslab; s++) {
        CP_WAIT1();
        __syncthreads();

        if (s + 2 < nslab) load_slab(s + 2, pbuf);
        CP_COMMIT();

        uint32_t sa = sbase + buf * STAGE_SB;
        uint32_t sb = sa + TILE_SB;
#pragma unroll
        for (int kk = 0; kk < 4; kk++) {
            uint32_t a[4][4];
#pragma unroll
            for (int i = 0; i < 4; i++) {
                uint32_t ad = sa + a_rb[i] + (uint32_t)((((cA0 + 2 * kk) ^ a_rs[i])) << 4);
                LDSM_X4(a[i][0], a[i][1], a[i][2], a[i][3], ad);
            }
            uint32_t b[4][2];
#pragma unroll
            for (int j = 0; j < 2; j++) {
                uint32_t bd = sb + b_rb[j] + (uint32_t)((((cB0 + 2 * kk) ^ b_rs[j])) << 4);
                uint32_t t0, t1, t2, t3;
                LDSM_X4(t0, t1, t2, t3, bd);
                b[2 * j][0] = t0; b[2 * j][1] = t1;
                b[2 * j + 1][0] = t2; b[2 * j + 1][1] = t3;
            }
#pragma unroll
            for (int i = 0; i < 4; i++)
#pragma unroll
                for (int j = 0; j < 4; j++)
                    MMA16816(acc[i][j], a[i], b[j]);
        }

        buf = (buf == 2) ? 0 : buf + 1;
        pbuf = (pbuf == 2) ? 0 : pbuf + 1;
    }

    // ---- epilogue ----
#pragma unroll
    for (int i = 0; i < 4; i++) {
        int r0 = m0 + warp_m + 16 * i + (lane >> 2);
#pragma unroll
        for (int j = 0; j < 4; j++) {
            int col = n0 + warp_n + 8 * j + (lane & 3) * 2;
            float b0v = bias[col], b1v = bias[col + 1];
            if (biasExtra) { b0v += biasExtra[col]; b1v += biasExtra[col + 1]; }
            float2* p0 = (float2*)(C + (size_t)r0 * Ntotal + col);
            float2* p1 = (float2*)(C + (size_t)(r0 + 8) * Ntotal + col);
            float2 v0; v0.x = acc[i][j][0] + b0v; v0.y = acc[i][j][1] + b1v;
            float2 v1; v1.x = acc[i][j][2] + b0v; v1.y = acc[i][j][3] + b1v;
            *p0 = v0;
            *p1 = v1;
        }
    }
}

// ============================================================
// Kernel 4: flash attention (fp32); merged local+global launch.
//   blockIdx.z: bit0 = batch, bit1 = branch (0=local, 1=global)
// ============================================================
#define FA_STRIDE 65
#define FA_SMEM_BYTES ((64 * FA_STRIDE * 2 + 64 * 64) * 4)

__global__ __launch_bounds__(256) void flash_kernel(
    const float* __restrict__ qkvl, const float* __restrict__ qkvg,
    __half* __restrict__ ao)
{
    extern __shared__ float sm[];
    float* Qst = sm;
    float* Kst = sm + 64 * FA_STRIDE;
    float* Vs  = sm + 2 * 64 * FA_STRIDE;

    int qt = blockIdx.x;
    int h  = blockIdx.y;
    int b  = blockIdx.z & 1;
    int is_global = blockIdx.z >> 1;
    int q0 = qt * 64;

    const float* qkv = is_global ? qkvg : qkvl;
    const float* base = qkv + (size_t)b * SLEN * QKVD;
    int qoff = h * DHEAD;
    int koff = DMODEL + h * DHEAD;
    int voff = 2 * DMODEL + h * DHEAD;

    int tid = threadIdx.x;
    int ty = tid >> 4;
    int tx = tid & 15;

#pragma unroll
    for (int i = 0; i < 4; i++) {
        int linear = tid + i * 256;
        int r = linear >> 4;
        int d = (linear & 15) * 4;
        float4 q4 = *(const float4*)(base + (size_t)(q0 + r) * QKVD + qoff + d);
        Qst[(d + 0) * FA_STRIDE + r] = q4.x;
        Qst[(d + 1) * FA_STRIDE + r] = q4.y;
        Qst[(d + 2) * FA_STRIDE + r] = q4.z;
        Qst[(d + 3) * FA_STRIDE + r] = q4.w;
    }

    float m_i[4], l_i[4], o[4][4];
#pragma unroll
    for (int i = 0; i < 4; i++) {
        m_i[i] = -1e30f; l_i[i] = 0.f;
#pragma unroll
        for (int j = 0; j < 4; j++) o[i][j] = 0.f;
    }

    int kt0, kt1;
    if (!is_global) { kt0 = (qt > 0) ? (qt - 1) : 0; kt1 = qt; }
    else            { kt0 = 0; kt1 = NQT - 1; }

    for (int kt = kt0; kt <= kt1; kt++) {
        __syncthreads();
        int k0 = kt * 64;
#pragma unroll
        for (int i = 0; i < 4; i++) {
            int linear = tid + i * 256;
            int r = linear >> 4;
            int d = (linear & 15) * 4;
            const float* krow = base + (size_t)(k0 + r) * QKVD;
            float4 k4 = *(const float4*)(krow + koff + d);
            Kst[(d + 0) * FA_STRIDE + r] = k4.x;
            Kst[(d + 1) * FA_STRIDE + r] = k4.y;
            Kst[(d + 2) * FA_STRIDE + r] = k4.z;
            Kst[(d + 3) * FA_STRIDE + r] = k4.w;
            float4 v4 = *(const float4*)(krow + voff + d);
            *(float4*)&Vs[r * 64 + d] = v4;
        }
        __syncthreads();

        float s[4][4];
#pragma unroll
        for (int i = 0; i < 4; i++)
#pragma unroll
            for (int j = 0; j < 4; j++) s[i][j] = 0.f;

#pragma unroll 4
        for (int k = 0; k < 64; k++) {
            float qv[4], kv[4];
#pragma unroll
            for (int i = 0; i < 4; i++) qv[i] = Qst[k * FA_STRIDE + ty * 4 + i];
#pragma unroll
            for (int j = 0; j < 4; j++) kv[j] = Kst[k * FA_STRIDE + tx * 4 + j];
#pragma unroll
            for (int i = 0; i < 4; i++)
#pragma unroll
                for (int j = 0; j < 4; j++)
                    s[i][j] += qv[i] * kv[j];
        }

#pragma unroll
        for (int i = 0; i < 4; i++) {
            float sc0 = s[i][0] * ATT_SCALE, sc1 = s[i][1] * ATT_SCALE;
            float sc2 = s[i][2] * ATT_SCALE, sc3 = s[i][3] * ATT_SCALE;
            float rm = fmaxf(fmaxf(sc0, sc1), fmaxf(sc2, sc3));
#pragma unroll
            for (int off = 8; off > 0; off >>= 1)
                rm = fmaxf(rm, __shfl_xor_sync(0xffffffffu, rm, off));
            float mnew = fmaxf(m_i[i], rm);
            float corr = __expf(m_i[i] - mnew);
            m_i[i] = mnew;
            float p0 = __expf(sc0 - mnew);
            float p1 = __expf(sc1 - mnew);
            float p2 = __expf(sc2 - mnew);
            float p3 = __expf(sc3 - mnew);
            s[i][0] = p0; s[i][1] = p1; s[i][2] = p2; s[i][3] = p3;
            float rs = p0 + p1 + p2 + p3;
#pragma unroll
            for (int off = 8; off > 0; off >>= 1)
                rs += __shfl_xor_sync(0xffffffffu, rs, off);
            l_i[i] = l_i[i] * corr + rs;
#pragma unroll
            for (int j = 0; j < 4; j++) o[i][j] *= corr;
        }

        __syncthreads();
#pragma unroll
        for (int i = 0; i < 4; i++)
#pragma unroll
            for (int j = 0; j < 4; j++)
                Kst[(ty * 4 + i) * FA_STRIDE + tx * 4 + j] = s[i][j];
        __syncthreads();

#pragma unroll 4
        for (int c = 0; c < 64; c++) {
            float4 v4 = *(const float4*)&Vs[c * 64 + tx * 4];
            float pr[4];
#pragma unroll
            for (int i = 0; i < 4; i++) pr[i] = Kst[(ty * 4 + i) * FA_STRIDE + c];
#pragma unroll
            for (int i = 0; i < 4; i++) {
                o[i][0] += pr[i] * v4.x;
                o[i][1] += pr[i] * v4.y;
                o[i][2] += pr[i] * v4.z;
                o[i][3] += pr[i] * v4.w;
            }
        }
    }

    int colofs = is_global ? DMODEL : 0;
#pragma unroll
    for (int i = 0; i < 4; i++) {
        float inv = 1.f / l_i[i];
        int r = q0 + ty * 4 + i;
        size_t dbase = (size_t)(b * SLEN + r) * KCAT + colofs + h * DHEAD + tx * 4;
        __half2 h0, h1;
        h0.x = __float2half(o[i][0] * inv); h0.y = __float2half(o[i][1] * inv);
        h1.x = __float2half(o[i][2] * inv); h1.y = __float2half(o[i][3] * inv);
        *(__half2*)&ao[dbase]     = h0;
        *(__half2*)&ao[dbase + 2] = h1;
    }
}

// ============================================================
// host launcher
// ============================================================
extern "C" void kernel_launch(void* const* d_in, const int* in_sizes, int n_in,
                              void* d_out, int out_size)
{
    const float* x      = (const float*)d_in[0];
    const float* ln_l_g = (const float*)d_in[1];
    const float* ln_l_b = (const float*)d_in[2];
    const float* Wqkv_l = (const float*)d_in[3];
    const float* bqkv_l = (const float*)d_in[4];
    const float* Wo_l   = (const float*)d_in[5];
    const float* bo_l   = (const float*)d_in[6];
    const float* ln_g_g = (const float*)d_in[7];
    const float* ln_g_b = (const float*)d_in[8];
    const float* Wqkv_g = (const float*)d_in[9];
    const float* bqkv_g = (const float*)d_in[10];
    const float* Wo_g   = (const float*)d_in[11];
    const float* bo_g   = (const float*)d_in[12];
    float* out = (float*)d_out;

    __half *xlf, *xgf, *wqlf, *wqgf, *wof, *aof;
    float *qkv_l, *qkv_g;
    cudaGetSymbolAddress((void**)&xlf, g_xlf);
    cudaGetSymbolAddress((void**)&xgf, g_xgf);
    cudaGetSymbolAddress((void**)&qkv_l, g_qkv_l);
    cudaGetSymbolAddress((void**)&qkv_g, g_qkv_g);
    cudaGetSymbolAddress((void**)&wqlf, g_wqkvl_f);
    cudaGetSymbolAddress((void**)&wqgf, g_wqkvg_f);
    cudaGetSymbolAddress((void**)&wof, g_wo_f);
    cudaGetSymbolAddress((void**)&aof, g_aof);

    cudaFuncSetAttribute(flash_kernel, cudaFuncAttributeMaxDynamicSharedMemorySize, FA_SMEM_BYTES);
    cudaFuncSetAttribute(gemm_f16, cudaFuncAttributeMaxDynamicSharedMemorySize, GEMM_SMEM);

    // 1) dual LN -> fp16
    ln_dual_kernel<<<NROWS, 256>>>(x, ln_l_g, ln_l_b, ln_g_g, ln_g_b, xlf, xgf);

    // 2) weight converts
    {
        int t4 = QKVD * DMODEL / 4;
        convert_f16<<<(t4 + 255) / 256, 256>>>(Wqkv_l, wqlf, DMODEL / 4, DMODEL, 0, t4);
        convert_f16<<<(t4 + 255) / 256, 256>>>(Wqkv_g, wqgf, DMODEL / 4, DMODEL, 0, t4);
        int t4o = DMODEL * DMODEL / 4;
        convert_f16<<<(t4o + 255) / 256, 256>>>(Wo_l, wof, DMODEL / 4, KCAT, 0, t4o);
        convert_f16<<<(t4o + 255) / 256, 256>>>(Wo_g, wof, DMODEL / 4, KCAT, DMODEL, t4o);
    }

    // 3) both QKV projections in ONE batched launch (z selects branch)
    {
        dim3 g(QKVD / GBN, NROWS / GBM, 2);
        gemm_f16<<<g, 256, GEMM_SMEM>>>(xlf, wqlf, bqkv_l, qkv_l,
                                        xgf, wqgf, bqkv_g, qkv_g,
                                        nullptr, QKVD, DMODEL);
    }

    // 4) merged local+global attention -> fp16 cat'd activation
    {
        dim3 gf(NQT, NHEAD, BATCH * 2);
        flash_kernel<<<gf, 256, FA_SMEM_BYTES>>>(qkv_l, qkv_g, aof);
    }

    // 5) single-pass fused out-projection: cat(ao) x cat(Wo)^T + bo_l + bo_g
    {
        dim3 g(DMODEL / GBN, NROWS / GBM, 1);
        gemm_f16<<<g, 256, GEMM_SMEM>>>(aof, wof, bo_l, out,
                                        aof, wof, bo_l, out,
                                        bo_g, DMODEL, KCAT);
    }
}

// round 9
// speedup vs baseline: 6.7691x; 3.1394x over previous
#include <cuda_runtime.h>
#include <cuda_fp16.h>
#include <math.h>
#include <stdint.h>

// ---------------- problem constants ----------------
#define BATCH   2
#define SLEN    2048
#define DMODEL  1024
#define NHEAD   16
#define DHEAD   64
#define NROWS   (BATCH * SLEN)          // 4096
#define QKVD    (3 * DMODEL)            // 3072
#define KCAT    (2 * DMODEL)            // 2048
#define NQT     (SLEN / 64)             // 32
#define ATT_SCALE 0.125f

// ---------------- scratch (device globals) ----------------
__device__ __align__(16) __half g_xlf[NROWS * DMODEL];
__device__ __align__(16) __half g_xgf[NROWS * DMODEL];
__device__ __align__(16) __half g_qkv_l[(size_t)NROWS * QKVD];   // fp16 now
__device__ __align__(16) __half g_qkv_g[(size_t)NROWS * QKVD];
__device__ __align__(16) __half g_wqkvl_f[QKVD * DMODEL];
__device__ __align__(16) __half g_wqkvg_f[QKVD * DMODEL];
__device__ __align__(16) __half g_wo_f[DMODEL * KCAT];
__device__ __align__(16) __half g_aof[(size_t)NROWS * KCAT];

__device__ __forceinline__ uint32_t smem_u32(const void* p) {
    uint32_t a;
    asm("{ .reg .u64 t; cvta.to.shared.u64 t, %1; cvt.u32.u64 %0, t; }" : "=r"(a) : "l"(p));
    return a;
}

#define LDSM_X4(r0, r1, r2, r3, a) \
    asm volatile("ldmatrix.sync.aligned.m8n8.x4.shared.b16 {%0,%1,%2,%3}, [%4];" \
                 : "=r"(r0), "=r"(r1), "=r"(r2), "=r"(r3) : "r"(a))

#define LDSM_X4_T(r0, r1, r2, r3, a) \
    asm volatile("ldmatrix.sync.aligned.m8n8.x4.trans.shared.b16 {%0,%1,%2,%3}, [%4];" \
                 : "=r"(r0), "=r"(r1), "=r"(r2), "=r"(r3) : "r"(a))

#define MMA16816(c, a, b) \
    asm volatile("mma.sync.aligned.m16n8k16.row.col.f32.f16.f16.f32 " \
                 "{%0,%1,%2,%3}, {%4,%5,%6,%7}, {%8,%9}, {%0,%1,%2,%3};" \
                 : "+f"((c)[0]), "+f"((c)[1]), "+f"((c)[2]), "+f"((c)[3]) \
                 : "r"((a)[0]), "r"((a)[1]), "r"((a)[2]), "r"((a)[3]), \
                   "r"((b)[0]), "r"((b)[1]))

#define CP_ASYNC16(s, g) \
    asm volatile("cp.async.cg.shared.global [%0], [%1], 16;" :: "r"(s), "l"(g))
#define CP_COMMIT() asm volatile("cp.async.commit_group;")
#define CP_WAIT0()  asm volatile("cp.async.wait_group 0;")
#define CP_WAIT1()  asm volatile("cp.async.wait_group 1;")

__device__ __forceinline__ uint32_t packf2(float lo, float hi) {
    __half2 h = __floats2half2_rn(lo, hi);
    return *(uint32_t*)&h;
}

// ============================================================
// Kernel 1: fused dual LayerNorm -> fp16 for both branches
// ============================================================
__global__ __launch_bounds__(256) void ln_dual_kernel(
    const float* __restrict__ x,
    const float* __restrict__ gl, const float* __restrict__ bl,
    const float* __restrict__ gg, const float* __restrict__ bg,
    __half* __restrict__ xl, __half* __restrict__ xg)
{
    int row = blockIdx.x;
    const float* xr = x + (size_t)row * DMODEL;
    int t = threadIdx.x;

    float v[4];
    float s = 0.f, s2 = 0.f;
#pragma unroll
    for (int i = 0; i < 4; i++) {
        float a = xr[t + i * 256];
        v[i] = a; s += a; s2 += a * a;
    }
#pragma unroll
    for (int o = 16; o > 0; o >>= 1) {
        s  += __shfl_xor_sync(0xffffffffu, s,  o);
        s2 += __shfl_xor_sync(0xffffffffu, s2, o);
    }
    __shared__ float red0[8], red1[8], stat[2];
    int warp = t >> 5, lane = t & 31;
    if (lane == 0) { red0[warp] = s; red1[warp] = s2; }
    __syncthreads();
    if (t < 32) {
        float a = (t < 8) ? red0[t] : 0.f;
        float b = (t < 8) ? red1[t] : 0.f;
#pragma unroll
        for (int o = 4; o > 0; o >>= 1) {
            a += __shfl_xor_sync(0xffffffffu, a, o);
            b += __shfl_xor_sync(0xffffffffu, b, o);
        }
        if (t == 0) {
            float mean = a * (1.f / DMODEL);
            float var  = b * (1.f / DMODEL) - mean * mean;
            stat[0] = mean;
            stat[1] = rsqrtf(var + 1e-5f);
        }
    }
    __syncthreads();
    float mean = stat[0], rstd = stat[1];
    size_t rb = (size_t)row * DMODEL;
#pragma unroll
    for (int i = 0; i < 4; i++) {
        int c = t + i * 256;
        float n = (v[i] - mean) * rstd;
        xl[rb + c] = __float2half(n * gl[c] + bl[c]);
        xg[rb + c] = __float2half(n * gg[c] + bg[c]);
    }
}

// ============================================================
// Kernel 2: weight convert fp32 -> fp16 (remapped destination)
// ============================================================
__global__ __launch_bounds__(256) void convert_f16(
    const float* __restrict__ src, __half* __restrict__ h,
    int cols4, int dstride, int doff, int total4)
{
    int idx = blockIdx.x * 256 + threadIdx.x;
    if (idx >= total4) return;
    int r = idx / cols4;
    int c4 = idx - r * cols4;
    float4 v = ((const float4*)src)[idx];
    size_t d = (size_t)r * dstride + doff + c4 * 4;
    __half2 h0, h1;
    h0.x = __float2half(v.x); h0.y = __float2half(v.y);
    h1.x = __float2half(v.z); h1.y = __float2half(v.w);
    *(__half2*)&h[d]     = h0;
    *(__half2*)&h[d + 2] = h1;
}

// ============================================================
// Kernel 3: fp16 single-pass GEMM (HMMA), optional fp16 output.
//   CTA 128x128, BK=64, 3-stage cp.async ring, XOR-swizzled smem.
//   blockIdx.z selects (A,B,bias,C) pair for batched launches.
// ============================================================
#define GBM 128
#define GBN 128
#define TILE_SB  16384
#define STAGE_SB 32768
#define NSTAGE   3
#define GEMM_SMEM (NSTAGE * STAGE_SB)

__global__ __launch_bounds__(256, 2) void gemm_f16(
    const __half* __restrict__ A0, const __half* __restrict__ B0,
    const float* __restrict__ bias0a, void* __restrict__ C0,
    const __half* __restrict__ A1, const __half* __restrict__ B1,
    const float* __restrict__ bias1a, void* __restrict__ C1,
    const float* __restrict__ biasExtra,
    int Ntotal, int K, int half_out)
{
    extern __shared__ char gsm[];
    uint32_t sbase = smem_u32(gsm);

    int tid = threadIdx.x;
    int m0 = blockIdx.y * GBM;
    int n0 = blockIdx.x * GBN;
    int lane = tid & 31;
    int wid = tid >> 5;
    int warp_m = (wid >> 2) * 64;
    int warp_n = (wid & 3) * 32;

    const __half* A = (blockIdx.z == 0) ? A0 : A1;
    const __half* B = (blockIdx.z == 0) ? B0 : B1;
    const float* bias = (blockIdx.z == 0) ? bias0a : bias1a;
    void* C = (blockIdx.z == 0) ? C0 : C1;

    int nslab = K >> 6;

    int l_row = tid >> 1;
    int l_c0  = (tid & 1) * 4;
    int l_sw  = l_row & 7;
    uint32_t l_sm_base = (uint32_t)(l_row * 128);

    float acc[4][4][4];
#pragma unroll
    for (int i = 0; i < 4; i++)
#pragma unroll
        for (int j = 0; j < 4; j++)
#pragma unroll
            for (int q = 0; q < 4; q++) acc[i][j][q] = 0.f;

    uint32_t a_rb[4]; int a_rs[4];
#pragma unroll
    for (int i = 0; i < 4; i++) {
        int r = warp_m + 16 * i + (lane & 15);
        a_rb[i] = (uint32_t)(r * 128);
        a_rs[i] = r & 7;
    }
    uint32_t b_rb[2]; int b_rs[2];
#pragma unroll
    for (int j = 0; j < 2; j++) {
        int r = warp_n + 16 * j + (lane & 7) + ((lane & 16) >> 1);
        b_rb[j] = (uint32_t)(r * 128);
        b_rs[j] = r & 7;
    }
    int cA0 = (lane >> 4);
    int cB0 = ((lane >> 3) & 1);

    auto load_slab = [&](int s, int buf) {
        int ks = s << 6;
        uint32_t sa = sbase + buf * STAGE_SB + l_sm_base;
        uint32_t sb = sa + TILE_SB;
        const __half* ga = A + (size_t)(m0 + l_row) * K + ks + l_c0 * 8;
        const __half* gb = B + (size_t)(n0 + l_row) * K + ks + l_c0 * 8;
#pragma unroll
        for (int q = 0; q < 4; q++) {
            int phys = ((l_c0 + q) ^ l_sw) << 4;
            CP_ASYNC16(sa + phys, ga + q * 8);
        }
#pragma unroll
        for (int q = 0; q < 4; q++) {
            int phys = ((l_c0 + q) ^ l_sw) << 4;
            CP_ASYNC16(sb + phys, gb + q * 8);
        }
    };

    load_slab(0, 0); CP_COMMIT();
    load_slab(1, 1); CP_COMMIT();

    int buf = 0, pbuf = 2;
    for (int s = 0; s < nslab; s++) {
        CP_WAIT1();
        __syncthreads();

        if (s + 2 < nslab) load_slab(s + 2, pbuf);
        CP_COMMIT();

        uint32_t sa = sbase + buf * STAGE_SB;
        uint32_t sb = sa + TILE_SB;
#pragma unroll
        for (int kk = 0; kk < 4; kk++) {
            uint32_t a[4][4];
#pragma unroll
            for (int i = 0; i < 4; i++) {
                uint32_t ad = sa + a_rb[i] + (uint32_t)((((cA0 + 2 * kk) ^ a_rs[i])) << 4);
                LDSM_X4(a[i][0], a[i][1], a[i][2], a[i][3], ad);
            }
            uint32_t b[4][2];
#pragma unroll
            for (int j = 0; j < 2; j++) {
                uint32_t bd = sb + b_rb[j] + (uint32_t)((((cB0 + 2 * kk) ^ b_rs[j])) << 4);
                uint32_t t0, t1, t2, t3;
                LDSM_X4(t0, t1, t2, t3, bd);
                b[2 * j][0] = t0; b[2 * j][1] = t1;
                b[2 * j + 1][0] = t2; b[2 * j + 1][1] = t3;
            }
#pragma unroll
            for (int i = 0; i < 4; i++)
#pragma unroll
                for (int j = 0; j < 4; j++)
                    MMA16816(acc[i][j], a[i], b[j]);
        }

        buf = (buf == 2) ? 0 : buf + 1;
        pbuf = (pbuf == 2) ? 0 : pbuf + 1;
    }

    // ---- epilogue ----
#pragma unroll
    for (int i = 0; i < 4; i++) {
        int r0 = m0 + warp_m + 16 * i + (lane >> 2);
#pragma unroll
        for (int j = 0; j < 4; j++) {
            int col = n0 + warp_n + 8 * j + (lane & 3) * 2;
            float b0v = bias[col], b1v = bias[col + 1];
            if (biasExtra) { b0v += biasExtra[col]; b1v += biasExtra[col + 1]; }
            float o00 = acc[i][j][0] + b0v, o01 = acc[i][j][1] + b1v;
            float o10 = acc[i][j][2] + b0v, o11 = acc[i][j][3] + b1v;
            if (half_out) {
                __half* Ch = (__half*)C;
                *(__half2*)(Ch + (size_t)r0 * Ntotal + col)       = __floats2half2_rn(o00, o01);
                *(__half2*)(Ch + (size_t)(r0 + 8) * Ntotal + col) = __floats2half2_rn(o10, o11);
            } else {
                float* Cf = (float*)C;
                float2 v0; v0.x = o00; v0.y = o01;
                float2 v1; v1.x = o10; v1.y = o11;
                *(float2*)(Cf + (size_t)r0 * Ntotal + col)       = v0;
                *(float2*)(Cf + (size_t)(r0 + 8) * Ntotal + col) = v1;
            }
        }
    }
}

// ============================================================
// Kernel 4: tensor-core flash attention (fp16 HMMA, fp32 softmax).
//   Grid (NQT, NHEAD, 4); z: bit0=batch, bit1=branch. 128 threads (4 warps).
//   Warp w: q rows [16w, 16w+16). Per tile: S = Q K^T, online softmax, O += P V.
// ============================================================
#define FS_Q 0
#define FS_K 8192
#define FS_V 16384

__global__ __launch_bounds__(128) void flash_tc_kernel(
    const __half* __restrict__ qkvl, const __half* __restrict__ qkvg,
    __half* __restrict__ ao)
{
    __shared__ __align__(128) char fs[24576];
    uint32_t sQ = smem_u32(fs) + FS_Q;
    uint32_t sK = smem_u32(fs) + FS_K;
    uint32_t sV = smem_u32(fs) + FS_V;

    int qt = blockIdx.x;
    int h  = blockIdx.y;
    int b  = blockIdx.z & 1;
    int is_global = blockIdx.z >> 1;
    int q0 = qt * 64;

    const __half* qkv = is_global ? qkvg : qkvl;
    const __half* base = qkv + (size_t)b * SLEN * QKVD;
    const __half* baseQ = base + h * DHEAD;
    const __half* baseK = base + DMODEL + h * DHEAD;
    const __half* baseV = base + 2 * DMODEL + h * DHEAD;

    int tid = threadIdx.x;
    int lane = tid & 31;
    int w = tid >> 5;

    // loader geometry (64 rows x 8 16B-chunks per tile; 128 thr x 4 chunks)
    int l_row = tid >> 1;
    int l_c0  = (tid & 1) * 4;
    int l_sw  = l_row & 7;
    uint32_t l_off = (uint32_t)(l_row * 128);

    // ---- load Q tile (swizzled) ----
    {
        const __half* gq = baseQ + (size_t)(q0 + l_row) * QKVD + l_c0 * 8;
#pragma unroll
        for (int q = 0; q < 4; q++)
            CP_ASYNC16(sQ + l_off + (((l_c0 + q) ^ l_sw) << 4), gq + q * 8);
        CP_COMMIT();
        CP_WAIT0();
    }
    __syncthreads();

    // ---- preload Q A-frags (scaled by ATT_SCALE, exact in fp16) ----
    uint32_t qf[4][4];
    {
        int r = w * 16 + (lane & 15);
        uint32_t rb = (uint32_t)(r * 128);
        int rs = r & 7;
        int cA0 = lane >> 4;
#pragma unroll
        for (int kk = 0; kk < 4; kk++) {
            uint32_t ad = sQ + rb + (uint32_t)(((cA0 + 2 * kk) ^ rs) << 4);
            LDSM_X4(qf[kk][0], qf[kk][1], qf[kk][2], qf[kk][3], ad);
            __half2 sc = __floats2half2_rn(ATT_SCALE, ATT_SCALE);
#pragma unroll
            for (int q = 0; q < 4; q++) {
                __half2 v = *(__half2*)&qf[kk][q];
                v = __hmul2(v, sc);
                qf[kk][q] = *(uint32_t*)&v;
            }
        }
    }

    // K-frag geometry: all 64 keys, 4 x4-loads per kstep
    uint32_t kb_rb[4]; int kb_rs[4];
#pragma unroll
    for (int jj = 0; jj < 4; jj++) {
        int r = 16 * jj + (lane & 7) + ((lane & 16) >> 1);
        kb_rb[jj] = (uint32_t)(r * 128);
        kb_rs[jj] = r & 7;
    }
    int cB0 = (lane >> 3) & 1;

    float oacc[8][4];
#pragma unroll
    for (int j = 0; j < 8; j++)
#pragma unroll
        for (int q = 0; q < 4; q++) oacc[j][q] = 0.f;
    float m0f = -1e30f, m1f = -1e30f, l0f = 0.f, l1f = 0.f;

    int kt0 = is_global ? 0 : ((qt > 0) ? qt - 1 : qt);
    int kt1 = is_global ? (NQT - 1) : qt;

    for (int kt = kt0; kt <= kt1; kt++) {
        int k0 = kt * 64;
        __syncthreads();   // previous tile's consumers done
        {
            const __half* gk = baseK + (size_t)(k0 + l_row) * QKVD + l_c0 * 8;
            const __half* gv = baseV + (size_t)(k0 + l_row) * QKVD + l_c0 * 8;
#pragma unroll
            for (int q = 0; q < 4; q++) {
                int phys = ((l_c0 + q) ^ l_sw) << 4;
                CP_ASYNC16(sK + l_off + phys, gk + q * 8);
                CP_ASYNC16(sV + l_off + phys, gv + q * 8);
            }
            CP_COMMIT();
            CP_WAIT0();
        }
        __syncthreads();

        // ---- S = (Q*scale) K^T : frags sacc[j], j = key-block 8j..8j+7 ----
        float sacc[8][4];
#pragma unroll
        for (int j = 0; j < 8; j++)
#pragma unroll
            for (int q = 0; q < 4; q++) sacc[j][q] = 0.f;
#pragma unroll
        for (int kk = 0; kk < 4; kk++) {
            uint32_t bfr[8][2];
#pragma unroll
            for (int jj = 0; jj < 4; jj++) {
                uint32_t bd = sK + kb_rb[jj] + (uint32_t)(((cB0 + 2 * kk) ^ kb_rs[jj]) << 4);
                uint32_t t0, t1, t2, t3;
                LDSM_X4(t0, t1, t2, t3, bd);
                bfr[2 * jj][0] = t0; bfr[2 * jj][1] = t1;
                bfr[2 * jj + 1][0] = t2; bfr[2 * jj + 1][1] = t3;
            }
#pragma unroll
            for (int j = 0; j < 8; j++)
                MMA16816(sacc[j], qf[kk], bfr[j]);
        }

        // ---- online softmax (rows r0 = 16w+(lane>>2), r1 = r0+8) ----
        float mx0 = -1e30f, mx1 = -1e30f;
#pragma unroll
        for (int j = 0; j < 8; j++) {
            mx0 = fmaxf(mx0, fmaxf(sacc[j][0], sacc[j][1]));
            mx1 = fmaxf(mx1, fmaxf(sacc[j][2], sacc[j][3]));
        }
        mx0 = fmaxf(mx0, __shfl_xor_sync(0xffffffffu, mx0, 1));
        mx0 = fmaxf(mx0, __shfl_xor_sync(0xffffffffu, mx0, 2));
        mx1 = fmaxf(mx1, __shfl_xor_sync(0xffffffffu, mx1, 1));
        mx1 = fmaxf(mx1, __shfl_xor_sync(0xffffffffu, mx1, 2));
        float mn0 = fmaxf(m0f, mx0), mn1 = fmaxf(m1f, mx1);
        float cr0 = __expf(m0f - mn0), cr1 = __expf(m1f - mn1);
        m0f = mn0; m1f = mn1;
        float rs0 = 0.f, rs1 = 0.f;
#pragma unroll
        for (int j = 0; j < 8; j++) {
            sacc[j][0] = __expf(sacc[j][0] - mn0);
            sacc[j][1] = __expf(sacc[j][1] - mn0);
            sacc[j][2] = __expf(sacc[j][2] - mn1);
            sacc[j][3] = __expf(sacc[j][3] - mn1);
            rs0 += sacc[j][0] + sacc[j][1];
            rs1 += sacc[j][2] + sacc[j][3];
        }
        rs0 += __shfl_xor_sync(0xffffffffu, rs0, 1);
        rs0 += __shfl_xor_sync(0xffffffffu, rs0, 2);
        rs1 += __shfl_xor_sync(0xffffffffu, rs1, 1);
        rs1 += __shfl_xor_sync(0xffffffffu, rs1, 2);
        l0f = l0f * cr0 + rs0;
        l1f = l1f * cr1 + rs1;
#pragma unroll
        for (int j = 0; j < 8; j++) {
            oacc[j][0] *= cr0; oacc[j][1] *= cr0;
            oacc[j][2] *= cr1; oacc[j][3] *= cr1;
        }

        // ---- O += P V  (P from sacc frags; V via ldmatrix.trans) ----
#pragma unroll
        for (int t = 0; t < 4; t++) {
            uint32_t pa[4];
            pa[0] = packf2(sacc[2 * t][0], sacc[2 * t][1]);
            pa[1] = packf2(sacc[2 * t][2], sacc[2 * t][3]);
            pa[2] = packf2(sacc[2 * t + 1][0], sacc[2 * t + 1][1]);
            pa[3] = packf2(sacc[2 * t + 1][2], sacc[2 * t + 1][3]);
            int kr = 16 * t + (lane & 15);
            int dc = (lane >> 4) << 3;        // 0 or 8
#pragma unroll
            for (int jj = 0; jj < 2; jj++) {
                // d16 block = 32*jj? No: 4 d16 groups; unroll 2x2
#pragma unroll
                for (int g = 0; g < 2; g++) {
                    int d16 = 16 * (2 * jj + g);
                    int chunk = (d16 + dc) >> 3;
                    uint32_t ad = sV + (uint32_t)(kr * 128) +
                                  (uint32_t)((chunk ^ (kr & 7)) << 4);
                    uint32_t r0, r1, r2, r3;
                    LDSM_X4_T(r0, r1, r2, r3, ad);
                    uint32_t vb0[2] = { r0, r1 };
                    uint32_t vb1[2] = { r2, r3 };
                    MMA16816(oacc[2 * (2 * jj + g)], pa, vb0);
                    MMA16816(oacc[2 * (2 * jj + g) + 1], pa, vb1);
                }
            }
        }
    }

    // ---- finalize: O /= l, write fp16 to cat'd ao ----
    float inv0 = 1.f / l0f, inv1 = 1.f / l1f;
    int colofs = is_global ? DMODEL : 0;
    int r0 = q0 + w * 16 + (lane >> 2);
    size_t db0 = (size_t)(b * SLEN + r0) * KCAT + colofs + h * DHEAD;
    size_t db1 = db0 + (size_t)8 * KCAT;
#pragma unroll
    for (int j = 0; j < 8; j++) {
        int col = 8 * j + (lane & 3) * 2;
        *(__half2*)&ao[db0 + col] = __floats2half2_rn(oacc[j][0] * inv0, oacc[j][1] * inv0);
        *(__half2*)&ao[db1 + col] = __floats2half2_rn(oacc[j][2] * inv1, oacc[j][3] * inv1);
    }
}

// ============================================================
// host launcher
// ============================================================
extern "C" void kernel_launch(void* const* d_in, const int* in_sizes, int n_in,
                              void* d_out, int out_size)
{
    const float* x      = (const float*)d_in[0];
    const float* ln_l_g = (const float*)d_in[1];
    const float* ln_l_b = (const float*)d_in[2];
    const float* Wqkv_l = (const float*)d_in[3];
    const float* bqkv_l = (const float*)d_in[4];
    const float* Wo_l   = (const float*)d_in[5];
    const float* bo_l   = (const float*)d_in[6];
    const float* ln_g_g = (const float*)d_in[7];
    const float* ln_g_b = (const float*)d_in[8];
    const float* Wqkv_g = (const float*)d_in[9];
    const float* bqkv_g = (const float*)d_in[10];
    const float* Wo_g   = (const float*)d_in[11];
    const float* bo_g   = (const float*)d_in[12];
    float* out = (float*)d_out;

    __half *xlf, *xgf, *wqlf, *wqgf, *wof, *aof, *qkv_l, *qkv_g;
    cudaGetSymbolAddress((void**)&xlf, g_xlf);
    cudaGetSymbolAddress((void**)&xgf, g_xgf);
    cudaGetSymbolAddress((void**)&qkv_l, g_qkv_l);
    cudaGetSymbolAddress((void**)&qkv_g, g_qkv_g);
    cudaGetSymbolAddress((void**)&wqlf, g_wqkvl_f);
    cudaGetSymbolAddress((void**)&wqgf, g_wqkvg_f);
    cudaGetSymbolAddress((void**)&wof, g_wo_f);
    cudaGetSymbolAddress((void**)&aof, g_aof);

    cudaFuncSetAttribute(gemm_f16, cudaFuncAttributeMaxDynamicSharedMemorySize, GEMM_SMEM);

    // 1) dual LN -> fp16
    ln_dual_kernel<<<NROWS, 256>>>(x, ln_l_g, ln_l_b, ln_g_g, ln_g_b, xlf, xgf);

    // 2) weight converts
    {
        int t4 = QKVD * DMODEL / 4;
        convert_f16<<<(t4 + 255) / 256, 256>>>(Wqkv_l, wqlf, DMODEL / 4, DMODEL, 0, t4);
        convert_f16<<<(t4 + 255) / 256, 256>>>(Wqkv_g, wqgf, DMODEL / 4, DMODEL, 0, t4);
        int t4o = DMODEL * DMODEL / 4;
        convert_f16<<<(t4o + 255) / 256, 256>>>(Wo_l, wof, DMODEL / 4, KCAT, 0, t4o);
        convert_f16<<<(t4o + 255) / 256, 256>>>(Wo_g, wof, DMODEL / 4, KCAT, DMODEL, t4o);
    }

    // 3) batched QKV projections, fp16 output
    {
        dim3 g(QKVD / GBN, NROWS / GBM, 2);
        gemm_f16<<<g, 256, GEMM_SMEM>>>(xlf, wqlf, bqkv_l, qkv_l,
                                        xgf, wqgf, bqkv_g, qkv_g,
                                        nullptr, QKVD, DMODEL, 1);
    }

    // 4) tensor-core flash (merged local+global) -> fp16 cat'd activation
    {
        dim3 gf(NQT, NHEAD, BATCH * 2);
        flash_tc_kernel<<<gf, 128>>>(qkv_l, qkv_g, aof);
    }

    // 5) single-pass fused out-projection -> fp32 out
    {
        dim3 g(DMODEL / GBN, NROWS / GBM, 1);
        gemm_f16<<<g, 256, GEMM_SMEM>>>(aof, wof, bo_l, out,
                                        aof, wof, bo_l, out,
                                        bo_g, DMODEL, KCAT, 0);
    }
}

// round 10
// speedup vs baseline: 7.0200x; 1.0371x over previous
#include <cuda_runtime.h>
#include <cuda_fp16.h>
#include <math.h>
#include <stdint.h>

// ---------------- problem constants ----------------
#define BATCH   2
#define SLEN    2048
#define DMODEL  1024
#define NHEAD   16
#define DHEAD   64
#define NROWS   (BATCH * SLEN)          // 4096
#define QKVD    (3 * DMODEL)            // 3072
#define KCAT    (2 * DMODEL)            // 2048
#define NQT     (SLEN / 64)             // 32 (64-row KV tiles)
#define NQT2    (SLEN / 128)            // 16 (128-row Q tiles)
#define ATT_SCALE 0.125f

// ---------------- scratch (device globals) ----------------
__device__ __align__(16) __half g_xlf[NROWS * DMODEL];
__device__ __align__(16) __half g_xgf[NROWS * DMODEL];
__device__ __align__(16) __half g_qkv_l[(size_t)NROWS * QKVD];
__device__ __align__(16) __half g_qkv_g[(size_t)NROWS * QKVD];
__device__ __align__(16) __half g_wqkvl_f[QKVD * DMODEL];
__device__ __align__(16) __half g_wqkvg_f[QKVD * DMODEL];
__device__ __align__(16) __half g_wo_f[DMODEL * KCAT];
__device__ __align__(16) __half g_aof[(size_t)NROWS * KCAT];

__device__ __forceinline__ uint32_t smem_u32(const void* p) {
    uint32_t a;
    asm("{ .reg .u64 t; cvta.to.shared.u64 t, %1; cvt.u32.u64 %0, t; }" : "=r"(a) : "l"(p));
    return a;
}

#define LDSM_X4(r0, r1, r2, r3, a) \
    asm volatile("ldmatrix.sync.aligned.m8n8.x4.shared.b16 {%0,%1,%2,%3}, [%4];" \
                 : "=r"(r0), "=r"(r1), "=r"(r2), "=r"(r3) : "r"(a))

#define LDSM_X4_T(r0, r1, r2, r3, a) \
    asm volatile("ldmatrix.sync.aligned.m8n8.x4.trans.shared.b16 {%0,%1,%2,%3}, [%4];" \
                 : "=r"(r0), "=r"(r1), "=r"(r2), "=r"(r3) : "r"(a))

#define MMA16816(c, a, b) \
    asm volatile("mma.sync.aligned.m16n8k16.row.col.f32.f16.f16.f32 " \
                 "{%0,%1,%2,%3}, {%4,%5,%6,%7}, {%8,%9}, {%0,%1,%2,%3};" \
                 : "+f"((c)[0]), "+f"((c)[1]), "+f"((c)[2]), "+f"((c)[3]) \
                 : "r"((a)[0]), "r"((a)[1]), "r"((a)[2]), "r"((a)[3]), \
                   "r"((b)[0]), "r"((b)[1]))

#define CP_ASYNC16(s, g) \
    asm volatile("cp.async.cg.shared.global [%0], [%1], 16;" :: "r"(s), "l"(g))
#define CP_COMMIT() asm volatile("cp.async.commit_group;")
#define CP_WAIT0()  asm volatile("cp.async.wait_group 0;")
#define CP_WAIT1()  asm volatile("cp.async.wait_group 1;")

__device__ __forceinline__ uint32_t packf2(float lo, float hi) {
    __half2 h = __floats2half2_rn(lo, hi);
    return *(uint32_t*)&h;
}

// ============================================================
// Kernel 1: fused dual LayerNorm -> fp16 for both branches
// ============================================================
__global__ __launch_bounds__(256) void ln_dual_kernel(
    const float* __restrict__ x,
    const float* __restrict__ gl, const float* __restrict__ bl,
    const float* __restrict__ gg, const float* __restrict__ bg,
    __half* __restrict__ xl, __half* __restrict__ xg)
{
    int row = blockIdx.x;
    const float* xr = x + (size_t)row * DMODEL;
    int t = threadIdx.x;

    float v[4];
    float s = 0.f, s2 = 0.f;
#pragma unroll
    for (int i = 0; i < 4; i++) {
        float a = xr[t + i * 256];
        v[i] = a; s += a; s2 += a * a;
    }
#pragma unroll
    for (int o = 16; o > 0; o >>= 1) {
        s  += __shfl_xor_sync(0xffffffffu, s,  o);
        s2 += __shfl_xor_sync(0xffffffffu, s2, o);
    }
    __shared__ float red0[8], red1[8], stat[2];
    int warp = t >> 5, lane = t & 31;
    if (lane == 0) { red0[warp] = s; red1[warp] = s2; }
    __syncthreads();
    if (t < 32) {
        float a = (t < 8) ? red0[t] : 0.f;
        float b = (t < 8) ? red1[t] : 0.f;
#pragma unroll
        for (int o = 4; o > 0; o >>= 1) {
            a += __shfl_xor_sync(0xffffffffu, a, o);
            b += __shfl_xor_sync(0xffffffffu, b, o);
        }
        if (t == 0) {
            float mean = a * (1.f / DMODEL);
            float var  = b * (1.f / DMODEL) - mean * mean;
            stat[0] = mean;
            stat[1] = rsqrtf(var + 1e-5f);
        }
    }
    __syncthreads();
    float mean = stat[0], rstd = stat[1];
    size_t rb = (size_t)row * DMODEL;
#pragma unroll
    for (int i = 0; i < 4; i++) {
        int c = t + i * 256;
        float n = (v[i] - mean) * rstd;
        xl[rb + c] = __float2half(n * gl[c] + bl[c]);
        xg[rb + c] = __float2half(n * gg[c] + bg[c]);
    }
}

// ============================================================
// Kernel 2: all four weight converts in ONE launch (z selects job)
// ============================================================
__global__ __launch_bounds__(256) void convert_all(
    const float* __restrict__ s0, __half* __restrict__ d0, int cs0, int ds0, int off0, int t0,
    const float* __restrict__ s1, __half* __restrict__ d1, int cs1, int ds1, int off1, int t1,
    const float* __restrict__ s2, __half* __restrict__ d2, int cs2, int ds2, int off2, int t2,
    const float* __restrict__ s3, __half* __restrict__ d3, int cs3, int ds3, int off3, int t3)
{
    const float* src; __half* h; int cols4, dstride, doff, total4;
    switch (blockIdx.z) {
        case 0: src = s0; h = d0; cols4 = cs0; dstride = ds0; doff = off0; total4 = t0; break;
        case 1: src = s1; h = d1; cols4 = cs1; dstride = ds1; doff = off1; total4 = t1; break;
        case 2: src = s2; h = d2; cols4 = cs2; dstride = ds2; doff = off2; total4 = t2; break;
        default: src = s3; h = d3; cols4 = cs3; dstride = ds3; doff = off3; total4 = t3; break;
    }
    int idx = blockIdx.x * 256 + threadIdx.x;
    if (idx >= total4) return;
    int r = idx / cols4;
    int c4 = idx - r * cols4;
    float4 v = ((const float4*)src)[idx];
    size_t d = (size_t)r * dstride + doff + c4 * 4;
    *(__half2*)&h[d]     = __floats2half2_rn(v.x, v.y);
    *(__half2*)&h[d + 2] = __floats2half2_rn(v.z, v.w);
}

// ============================================================
// Kernel 3: fp16 single-pass GEMM (HMMA), optional fp16 output.
//   CTA 128x128, BK=64, 3-stage cp.async ring, XOR-swizzled smem.
// ============================================================
#define GBM 128
#define GBN 128
#define TILE_SB  16384
#define STAGE_SB 32768
#define NSTAGE   3
#define GEMM_SMEM (NSTAGE * STAGE_SB)

__global__ __launch_bounds__(256, 2) void gemm_f16(
    const __half* __restrict__ A0, const __half* __restrict__ B0,
    const float* __restrict__ bias0a, void* __restrict__ C0,
    const __half* __restrict__ A1, const __half* __restrict__ B1,
    const float* __restrict__ bias1a, void* __restrict__ C1,
    const float* __restrict__ biasExtra,
    int Ntotal, int K, int half_out)
{
    extern __shared__ char gsm[];
    uint32_t sbase = smem_u32(gsm);

    int tid = threadIdx.x;
    int m0 = blockIdx.y * GBM;
    int n0 = blockIdx.x * GBN;
    int lane = tid & 31;
    int wid = tid >> 5;
    int warp_m = (wid >> 2) * 64;
    int warp_n = (wid & 3) * 32;

    const __half* A = (blockIdx.z == 0) ? A0 : A1;
    const __half* B = (blockIdx.z == 0) ? B0 : B1;
    const float* bias = (blockIdx.z == 0) ? bias0a : bias1a;
    void* C = (blockIdx.z == 0) ? C0 : C1;

    int nslab = K >> 6;

    int l_row = tid >> 1;
    int l_c0  = (tid & 1) * 4;
    int l_sw  = l_row & 7;
    uint32_t l_sm_base = (uint32_t)(l_row * 128);

    float acc[4][4][4];
#pragma unroll
    for (int i = 0; i < 4; i++)
#pragma unroll
        for (int j = 0; j < 4; j++)
#pragma unroll
            for (int q = 0; q < 4; q++) acc[i][j][q] = 0.f;

    uint32_t a_rb[4]; int a_rs[4];
#pragma unroll
    for (int i = 0; i < 4; i++) {
        int r = warp_m + 16 * i + (lane & 15);
        a_rb[i] = (uint32_t)(r * 128);
        a_rs[i] = r & 7;
    }
    uint32_t b_rb[2]; int b_rs[2];
#pragma unroll
    for (int j = 0; j < 2; j++) {
        int r = warp_n + 16 * j + (lane & 7) + ((lane & 16) >> 1);
        b_rb[j] = (uint32_t)(r * 128);
        b_rs[j] = r & 7;
    }
    int cA0 = (lane >> 4);
    int cB0 = ((lane >> 3) & 1);

    auto load_slab = [&](int s, int buf) {
        int ks = s << 6;
        uint32_t sa = sbase + buf * STAGE_SB + l_sm_base;
        uint32_t sb = sa + TILE_SB;
        const __half* ga = A + (size_t)(m0 + l_row) * K + ks + l_c0 * 8;
        const __half* gb = B + (size_t)(n0 + l_row) * K + ks + l_c0 * 8;
#pragma unroll
        for (int q = 0; q < 4; q++) {
            int phys = ((l_c0 + q) ^ l_sw) << 4;
            CP_ASYNC16(sa + phys, ga + q * 8);
        }
#pragma unroll
        for (int q = 0; q < 4; q++) {
            int phys = ((l_c0 + q) ^ l_sw) << 4;
            CP_ASYNC16(sb + phys, gb + q * 8);
        }
    };

    load_slab(0, 0); CP_COMMIT();
    load_slab(1, 1); CP_COMMIT();

    int buf = 0, pbuf = 2;
    for (int s = 0; s < nslab; s++) {
        CP_WAIT1();
        __syncthreads();

        if (s + 2 < nslab) load_slab(s + 2, pbuf);
        CP_COMMIT();

        uint32_t sa = sbase + buf * STAGE_SB;
        uint32_t sb = sa + TILE_SB;
#pragma unroll
        for (int kk = 0; kk < 4; kk++) {
            uint32_t a[4][4];
#pragma unroll
            for (int i = 0; i < 4; i++) {
                uint32_t ad = sa + a_rb[i] + (uint32_t)((((cA0 + 2 * kk) ^ a_rs[i])) << 4);
                LDSM_X4(a[i][0], a[i][1], a[i][2], a[i][3], ad);
            }
            uint32_t b[4][2];
#pragma unroll
            for (int j = 0; j < 2; j++) {
                uint32_t bd = sb + b_rb[j] + (uint32_t)((((cB0 + 2 * kk) ^ b_rs[j])) << 4);
                uint32_t t0, t1, t2, t3;
                LDSM_X4(t0, t1, t2, t3, bd);
                b[2 * j][0] = t0; b[2 * j][1] = t1;
                b[2 * j + 1][0] = t2; b[2 * j + 1][1] = t3;
            }
#pragma unroll
            for (int i = 0; i < 4; i++)
#pragma unroll
                for (int j = 0; j < 4; j++)
                    MMA16816(acc[i][j], a[i], b[j]);
        }

        buf = (buf == 2) ? 0 : buf + 1;
        pbuf = (pbuf == 2) ? 0 : pbuf + 1;
    }

    // ---- epilogue ----
#pragma unroll
    for (int i = 0; i < 4; i++) {
        int r0 = m0 + warp_m + 16 * i + (lane >> 2);
#pragma unroll
        for (int j = 0; j < 4; j++) {
            int col = n0 + warp_n + 8 * j + (lane & 3) * 2;
            float b0v = bias[col], b1v = bias[col + 1];
            if (biasExtra) { b0v += biasExtra[col]; b1v += biasExtra[col + 1]; }
            float o00 = acc[i][j][0] + b0v, o01 = acc[i][j][1] + b1v;
            float o10 = acc[i][j][2] + b0v, o11 = acc[i][j][3] + b1v;
            if (half_out) {
                __half* Ch = (__half*)C;
                *(__half2*)(Ch + (size_t)r0 * Ntotal + col)       = __floats2half2_rn(o00, o01);
                *(__half2*)(Ch + (size_t)(r0 + 8) * Ntotal + col) = __floats2half2_rn(o10, o11);
            } else {
                float* Cf = (float*)C;
                float2 v0; v0.x = o00; v0.y = o01;
                float2 v1; v1.x = o10; v1.y = o11;
                *(float2*)(Cf + (size_t)r0 * Ntotal + col)       = v0;
                *(float2*)(Cf + (size_t)(r0 + 8) * Ntotal + col) = v1;
            }
        }
    }
}

// ============================================================
// Kernel 4: tensor-core flash, 128-query tiles, double-buffered K/V.
//   Grid (NQT2=16, NHEAD, 4); z: bit0=batch, bit1=branch. 256 threads.
//   Warp w owns q rows [16w,16w+16). Local branch: warps 0-3 = chunk 2qt
//   (KV chunks {2qt-1,2qt}), warps 4-7 = chunk 2qt+1 (KV {2qt,2qt+1}).
// ============================================================
#define FS2_Q   0
#define FS2_K0  16384
#define FS2_K1  24576
#define FS2_V0  32768
#define FS2_V1  40960
#define FS2_TOTAL 49152

__global__ __launch_bounds__(256) void flash_tc_kernel(
    const __half* __restrict__ qkvl, const __half* __restrict__ qkvg,
    __half* __restrict__ ao)
{
    extern __shared__ char fs[];
    uint32_t sbase = smem_u32(fs);
    uint32_t sQ = sbase + FS2_Q;
    uint32_t sKb[2] = { sbase + FS2_K0, sbase + FS2_K1 };
    uint32_t sVb[2] = { sbase + FS2_V0, sbase + FS2_V1 };

    int qt = blockIdx.x;
    int h  = blockIdx.y;
    int b  = blockIdx.z & 1;
    int is_global = blockIdx.z >> 1;
    int q0 = qt * 128;

    const __half* qkv = is_global ? qkvg : qkvl;
    const __half* base = qkv + (size_t)b * SLEN * QKVD;
    const __half* baseQ = base + h * DHEAD;
    const __half* baseK = base + DMODEL + h * DHEAD;
    const __half* baseV = base + 2 * DMODEL + h * DHEAD;

    int tid = threadIdx.x;
    int lane = tid & 31;
    int w = tid >> 5;
    int half = w >> 2;

    // ---- load Q tile (128 rows x 128B; 4 chunks/thread, swizzled) ----
    {
        int l_row = tid >> 1;
        int l_c0  = (tid & 1) * 4;
        int l_sw  = l_row & 7;
        uint32_t l_off = (uint32_t)(l_row * 128);
        const __half* gq = baseQ + (size_t)(q0 + l_row) * QKVD + l_c0 * 8;
#pragma unroll
        for (int q = 0; q < 4; q++)
            CP_ASYNC16(sQ + l_off + (((l_c0 + q) ^ l_sw) << 4), gq + q * 8);
        CP_COMMIT();
        CP_WAIT0();
    }
    __syncthreads();

    // ---- preload Q A-frags (scaled by ATT_SCALE) ----
    uint32_t qf[4][4];
    {
        int r = w * 16 + (lane & 15);
        uint32_t rb = (uint32_t)(r * 128);
        int rs = r & 7;
        int cA0 = lane >> 4;
        __half2 sc = __floats2half2_rn(ATT_SCALE, ATT_SCALE);
#pragma unroll
        for (int kk = 0; kk < 4; kk++) {
            uint32_t ad = sQ + rb + (uint32_t)(((cA0 + 2 * kk) ^ rs) << 4);
            LDSM_X4(qf[kk][0], qf[kk][1], qf[kk][2], qf[kk][3], ad);
#pragma unroll
            for (int q = 0; q < 4; q++) {
                __half2 v = *(__half2*)&qf[kk][q];
                v = __hmul2(v, sc);
                qf[kk][q] = *(uint32_t*)&v;
            }
        }
    }

    // ---- K/V loader geometry (64 rows x 8 chunks; 2 chunks/thread each) ----
    int k_row = tid >> 2;
    int k_c0  = (tid & 3) * 2;
    int k_sw  = k_row & 7;
    uint32_t k_off = (uint32_t)(k_row * 128);

    // K-frag geometry
    uint32_t kb_rb[4]; int kb_rs[4];
#pragma unroll
    for (int jj = 0; jj < 4; jj++) {
        int r = 16 * jj + (lane & 7) + ((lane & 16) >> 1);
        kb_rb[jj] = (uint32_t)(r * 128);
        kb_rs[jj] = r & 7;
    }
    int cB0 = (lane >> 3) & 1;

    float oacc[8][4];
#pragma unroll
    for (int j = 0; j < 8; j++)
#pragma unroll
        for (int q = 0; q < 4; q++) oacc[j][q] = 0.f;
    float m0f = -1e30f, m1f = -1e30f, l0f = 0.f, l1f = 0.f;

    int kt_lo, kt_hi, wlo, whi;
    if (is_global) {
        kt_lo = 0; kt_hi = NQT - 1; wlo = kt_lo; whi = kt_hi;
    } else {
        kt_lo = (2 * qt - 1 > 0) ? 2 * qt - 1 : 0;
        kt_hi = 2 * qt + 1;
        if (half == 0) { wlo = kt_lo; whi = 2 * qt; }
        else           { wlo = 2 * qt; whi = 2 * qt + 1; }
    }

    auto load_kv = [&](int kt, int bufi) {
        int k0r = kt * 64;
        const __half* gk = baseK + (size_t)(k0r + k_row) * QKVD + k_c0 * 8;
        const __half* gv = baseV + (size_t)(k0r + k_row) * QKVD + k_c0 * 8;
#pragma unroll
        for (int q = 0; q < 2; q++) {
            int phys = ((k_c0 + q) ^ k_sw) << 4;
            CP_ASYNC16(sKb[bufi] + k_off + phys, gk + q * 8);
            CP_ASYNC16(sVb[bufi] + k_off + phys, gv + q * 8);
        }
    };

    load_kv(kt_lo, 0); CP_COMMIT();

    int buf = 0;
    for (int kt = kt_lo; kt <= kt_hi; kt++) {
        __syncthreads();                   // all warps done with buf^1 (iter kt-1)
        if (kt + 1 <= kt_hi) {
            load_kv(kt + 1, buf ^ 1);
            CP_COMMIT();
            CP_WAIT1();                    // tile kt's group complete
        } else {
            CP_WAIT0();
        }
        __syncthreads();                   // tile kt visible to all warps

        if (kt >= wlo && kt <= whi) {
            uint32_t sK = sKb[buf], sV = sVb[buf];

            // ---- S = (Q*scale) K^T ----
            float sacc[8][4];
#pragma unroll
            for (int j = 0; j < 8; j++)
#pragma unroll
                for (int q = 0; q < 4; q++) sacc[j][q] = 0.f;
#pragma unroll
            for (int kk = 0; kk < 4; kk++) {
                uint32_t bfr[8][2];
#pragma unroll
                for (int jj = 0; jj < 4; jj++) {
                    uint32_t bd = sK + kb_rb[jj] + (uint32_t)(((cB0 + 2 * kk) ^ kb_rs[jj]) << 4);
                    uint32_t t0, t1, t2, t3;
                    LDSM_X4(t0, t1, t2, t3, bd);
                    bfr[2 * jj][0] = t0; bfr[2 * jj][1] = t1;
                    bfr[2 * jj + 1][0] = t2; bfr[2 * jj + 1][1] = t3;
                }
#pragma unroll
                for (int j = 0; j < 8; j++)
                    MMA16816(sacc[j], qf[kk], bfr[j]);
            }

            // ---- online softmax ----
            float mx0 = -1e30f, mx1 = -1e30f;
#pragma unroll
            for (int j = 0; j < 8; j++) {
                mx0 = fmaxf(mx0, fmaxf(sacc[j][0], sacc[j][1]));
                mx1 = fmaxf(mx1, fmaxf(sacc[j][2], sacc[j][3]));
            }
            mx0 = fmaxf(mx0, __shfl_xor_sync(0xffffffffu, mx0, 1));
            mx0 = fmaxf(mx0, __shfl_xor_sync(0xffffffffu, mx0, 2));
            mx1 = fmaxf(mx1, __shfl_xor_sync(0xffffffffu, mx1, 1));
            mx1 = fmaxf(mx1, __shfl_xor_sync(0xffffffffu, mx1, 2));
            float mn0 = fmaxf(m0f, mx0), mn1 = fmaxf(m1f, mx1);
            float cr0 = __expf(m0f - mn0), cr1 = __expf(m1f - mn1);
            m0f = mn0; m1f = mn1;
            float rs0 = 0.f, rs1 = 0.f;
#pragma unroll
            for (int j = 0; j < 8; j++) {
                sacc[j][0] = __expf(sacc[j][0] - mn0);
                sacc[j][1] = __expf(sacc[j][1] - mn0);
                sacc[j][2] = __expf(sacc[j][2] - mn1);
                sacc[j][3] = __expf(sacc[j][3] - mn1);
                rs0 += sacc[j][0] + sacc[j][1];
                rs1 += sacc[j][2] + sacc[j][3];
            }
            rs0 += __shfl_xor_sync(0xffffffffu, rs0, 1);
            rs0 += __shfl_xor_sync(0xffffffffu, rs0, 2);
            rs1 += __shfl_xor_sync(0xffffffffu, rs1, 1);
            rs1 += __shfl_xor_sync(0xffffffffu, rs1, 2);
            l0f = l0f * cr0 + rs0;
            l1f = l1f * cr1 + rs1;
#pragma unroll
            for (int j = 0; j < 8; j++) {
                oacc[j][0] *= cr0; oacc[j][1] *= cr0;
                oacc[j][2] *= cr1; oacc[j][3] *= cr1;
            }

            // ---- O += P V ----
#pragma unroll
            for (int t = 0; t < 4; t++) {
                uint32_t pa[4];
                pa[0] = packf2(sacc[2 * t][0], sacc[2 * t][1]);
                pa[1] = packf2(sacc[2 * t][2], sacc[2 * t][3]);
                pa[2] = packf2(sacc[2 * t + 1][0], sacc[2 * t + 1][1]);
                pa[3] = packf2(sacc[2 * t + 1][2], sacc[2 * t + 1][3]);
                int kr = 16 * t + (lane & 15);
                int dc = (lane >> 4) << 3;
#pragma unroll
                for (int g = 0; g < 4; g++) {
                    int d16 = 16 * g;
                    int chunk = (d16 + dc) >> 3;
                    uint32_t ad = sV + (uint32_t)(kr * 128) +
                                  (uint32_t)((chunk ^ (kr & 7)) << 4);
                    uint32_t r0, r1, r2, r3;
                    LDSM_X4_T(r0, r1, r2, r3, ad);
                    uint32_t vb0[2] = { r0, r1 };
                    uint32_t vb1[2] = { r2, r3 };
                    MMA16816(oacc[2 * g], pa, vb0);
                    MMA16816(oacc[2 * g + 1], pa, vb1);
                }
            }
        }
        buf ^= 1;
    }

    // ---- finalize ----
    float inv0 = 1.f / l0f, inv1 = 1.f / l1f;
    int colofs = is_global ? DMODEL : 0;
    int r0 = q0 + w * 16 + (lane >> 2);
    size_t db0 = (size_t)(b * SLEN + r0) * KCAT + colofs + h * DHEAD;
    size_t db1 = db0 + (size_t)8 * KCAT;
#pragma unroll
    for (int j = 0; j < 8; j++) {
        int col = 8 * j + (lane & 3) * 2;
        *(__half2*)&ao[db0 + col] = __floats2half2_rn(oacc[j][0] * inv0, oacc[j][1] * inv0);
        *(__half2*)&ao[db1 + col] = __floats2half2_rn(oacc[j][2] * inv1, oacc[j][3] * inv1);
    }
}

// ============================================================
// host launcher
// ============================================================
extern "C" void kernel_launch(void* const* d_in, const int* in_sizes, int n_in,
                              void* d_out, int out_size)
{
    const float* x      = (const float*)d_in[0];
    const float* ln_l_g = (const float*)d_in[1];
    const float* ln_l_b = (const float*)d_in[2];
    const float* Wqkv_l = (const float*)d_in[3];
    const float* bqkv_l = (const float*)d_in[4];
    const float* Wo_l   = (const float*)d_in[5];
    const float* bo_l   = (const float*)d_in[6];
    const float* ln_g_g = (const float*)d_in[7];
    const float* ln_g_b = (const float*)d_in[8];
    const float* Wqkv_g = (const float*)d_in[9];
    const float* bqkv_g = (const float*)d_in[10];
    const float* Wo_g   = (const float*)d_in[11];
    const float* bo_g   = (const float*)d_in[12];
    float* out = (float*)d_out;

    __half *xlf, *xgf, *wqlf, *wqgf, *wof, *aof, *qkv_l, *qkv_g;
    cudaGetSymbolAddress((void**)&xlf, g_xlf);
    cudaGetSymbolAddress((void**)&xgf, g_xgf);
    cudaGetSymbolAddress((void**)&qkv_l, g_qkv_l);
    cudaGetSymbolAddress((void**)&qkv_g, g_qkv_g);
    cudaGetSymbolAddress((void**)&wqlf, g_wqkvl_f);
    cudaGetSymbolAddress((void**)&wqgf, g_wqkvg_f);
    cudaGetSymbolAddress((void**)&wof, g_wo_f);
    cudaGetSymbolAddress((void**)&aof, g_aof);

    cudaFuncSetAttribute(gemm_f16, cudaFuncAttributeMaxDynamicSharedMemorySize, GEMM_SMEM);
    cudaFuncSetAttribute(flash_tc_kernel, cudaFuncAttributeMaxDynamicSharedMemorySize, FS2_TOTAL);

    // 1) dual LN -> fp16
    ln_dual_kernel<<<NROWS, 256>>>(x, ln_l_g, ln_l_b, ln_g_g, ln_g_b, xlf, xgf);

    // 2) all weight converts in one launch
    {
        int tq = QKVD * DMODEL / 4;      // 786432
        int to = DMODEL * DMODEL / 4;    // 262144
        dim3 g((tq + 255) / 256, 1, 4);
        convert_all<<<g, 256>>>(
            Wqkv_l, wqlf, DMODEL / 4, DMODEL, 0, tq,
            Wqkv_g, wqgf, DMODEL / 4, DMODEL, 0, tq,
            Wo_l,   wof,  DMODEL / 4, KCAT,  0, to,
            Wo_g,   wof,  DMODEL / 4, KCAT,  DMODEL, to);
    }

    // 3) batched QKV projections, fp16 output
    {
        dim3 g(QKVD / GBN, NROWS / GBM, 2);
        gemm_f16<<<g, 256, GEMM_SMEM>>>(xlf, wqlf, bqkv_l, qkv_l,
                                        xgf, wqgf, bqkv_g, qkv_g,
                                        nullptr, QKVD, DMODEL, 1);
    }

    // 4) tensor-core flash, 128-q tiles, double-buffered KV
    {
        dim3 gf(NQT2, NHEAD, BATCH * 2);
        flash_tc_kernel<<<gf, 256, FS2_TOTAL>>>(qkv_l, qkv_g, aof);
    }

    // 5) single-pass fused out-projection -> fp32 out
    {
        dim3 g(DMODEL / GBN, NROWS / GBM, 1);
        gemm_f16<<<g, 256, GEMM_SMEM>>>(aof, wof, bo_l, out,
                                        aof, wof, bo_l, out,
                                        bo_g, DMODEL, KCAT, 0);
    }
}

// round 11
// speedup vs baseline: 7.3250x; 1.0434x over previous
#include <cuda_runtime.h>
#include <cuda_fp16.h>
#include <math.h>
#include <stdint.h>

// ---------------- problem constants ----------------
#define BATCH   2
#define SLEN    2048
#define DMODEL  1024
#define NHEAD   16
#define DHEAD   64
#define NROWS   (BATCH * SLEN)          // 4096
#define QKVD    (3 * DMODEL)            // 3072
#define KCAT    (2 * DMODEL)            // 2048
#define NQT     (SLEN / 64)             // 32 (64-row KV tiles)
#define NQT2    (SLEN / 128)            // 16 (128-row Q tiles)
#define ATT_SCALE 0.125f
#define QSCALE  (0.125f * 1.4426950408889634f)   // scale * log2(e)

// ---------------- scratch (device globals) ----------------
__device__ __align__(16) __half g_xlf[NROWS * DMODEL];
__device__ __align__(16) __half g_xgf[NROWS * DMODEL];
__device__ __align__(16) __half g_qkv_l[(size_t)NROWS * QKVD];
__device__ __align__(16) __half g_qkv_g[(size_t)NROWS * QKVD];
__device__ __align__(16) __half g_wqkvl_f[QKVD * DMODEL];
__device__ __align__(16) __half g_wqkvg_f[QKVD * DMODEL];
__device__ __align__(16) __half g_wo_f[DMODEL * KCAT];
__device__ __align__(16) __half g_aof[(size_t)NROWS * KCAT];

__device__ __forceinline__ uint32_t smem_u32(const void* p) {
    uint32_t a;
    asm("{ .reg .u64 t; cvta.to.shared.u64 t, %1; cvt.u32.u64 %0, t; }" : "=r"(a) : "l"(p));
    return a;
}

__device__ __forceinline__ float ex2(float x) {
    float y;
    asm("ex2.approx.f32 %0, %1;" : "=f"(y) : "f"(x));
    return y;
}

#define LDSM_X4(r0, r1, r2, r3, a) \
    asm volatile("ldmatrix.sync.aligned.m8n8.x4.shared.b16 {%0,%1,%2,%3}, [%4];" \
                 : "=r"(r0), "=r"(r1), "=r"(r2), "=r"(r3) : "r"(a))

#define LDSM_X4_T(r0, r1, r2, r3, a) \
    asm volatile("ldmatrix.sync.aligned.m8n8.x4.trans.shared.b16 {%0,%1,%2,%3}, [%4];" \
                 : "=r"(r0), "=r"(r1), "=r"(r2), "=r"(r3) : "r"(a))

#define MMA16816(c, a, b) \
    asm volatile("mma.sync.aligned.m16n8k16.row.col.f32.f16.f16.f32 " \
                 "{%0,%1,%2,%3}, {%4,%5,%6,%7}, {%8,%9}, {%0,%1,%2,%3};" \
                 : "+f"((c)[0]), "+f"((c)[1]), "+f"((c)[2]), "+f"((c)[3]) \
                 : "r"((a)[0]), "r"((a)[1]), "r"((a)[2]), "r"((a)[3]), \
                   "r"((b)[0]), "r"((b)[1]))

#define CP_ASYNC16(s, g) \
    asm volatile("cp.async.cg.shared.global [%0], [%1], 16;" :: "r"(s), "l"(g))
#define CP_COMMIT() asm volatile("cp.async.commit_group;")
#define CP_WAIT0()  asm volatile("cp.async.wait_group 0;")
#define CP_WAIT1()  asm volatile("cp.async.wait_group 1;")
#define CP_WAIT2()  asm volatile("cp.async.wait_group 2;")

__device__ __forceinline__ uint32_t packf2(float lo, float hi) {
    __half2 h = __floats2half2_rn(lo, hi);
    return *(uint32_t*)&h;
}

// ============================================================
// Kernel 1: fused dual LayerNorm -> fp16 for both branches
// ============================================================
__global__ __launch_bounds__(256) void ln_dual_kernel(
    const float* __restrict__ x,
    const float* __restrict__ gl, const float* __restrict__ bl,
    const float* __restrict__ gg, const float* __restrict__ bg,
    __half* __restrict__ xl, __half* __restrict__ xg)
{
    int row = blockIdx.x;
    const float* xr = x + (size_t)row * DMODEL;
    int t = threadIdx.x;

    float v[4];
    float s = 0.f, s2 = 0.f;
#pragma unroll
    for (int i = 0; i < 4; i++) {
        float a = xr[t + i * 256];
        v[i] = a; s += a; s2 += a * a;
    }
#pragma unroll
    for (int o = 16; o > 0; o >>= 1) {
        s  += __shfl_xor_sync(0xffffffffu, s,  o);
        s2 += __shfl_xor_sync(0xffffffffu, s2, o);
    }
    __shared__ float red0[8], red1[8], stat[2];
    int warp = t >> 5, lane = t & 31;
    if (lane == 0) { red0[warp] = s; red1[warp] = s2; }
    __syncthreads();
    if (t < 32) {
        float a = (t < 8) ? red0[t] : 0.f;
        float b = (t < 8) ? red1[t] : 0.f;
#pragma unroll
        for (int o = 4; o > 0; o >>= 1) {
            a += __shfl_xor_sync(0xffffffffu, a, o);
            b += __shfl_xor_sync(0xffffffffu, b, o);
        }
        if (t == 0) {
            float mean = a * (1.f / DMODEL);
            float var  = b * (1.f / DMODEL) - mean * mean;
            stat[0] = mean;
            stat[1] = rsqrtf(var + 1e-5f);
        }
    }
    __syncthreads();
    float mean = stat[0], rstd = stat[1];
    size_t rb = (size_t)row * DMODEL;
#pragma unroll
    for (int i = 0; i < 4; i++) {
        int c = t + i * 256;
        float n = (v[i] - mean) * rstd;
        xl[rb + c] = __float2half(n * gl[c] + bl[c]);
        xg[rb + c] = __float2half(n * gg[c] + bg[c]);
    }
}

// ============================================================
// Kernel 2: all four weight converts in ONE launch (z selects job)
// ============================================================
__global__ __launch_bounds__(256) void convert_all(
    const float* __restrict__ s0, __half* __restrict__ d0, int cs0, int ds0, int off0, int t0,
    const float* __restrict__ s1, __half* __restrict__ d1, int cs1, int ds1, int off1, int t1,
    const float* __restrict__ s2, __half* __restrict__ d2, int cs2, int ds2, int off2, int t2,
    const float* __restrict__ s3, __half* __restrict__ d3, int cs3, int ds3, int off3, int t3)
{
    const float* src; __half* h; int cols4, dstride, doff, total4;
    switch (blockIdx.z) {
        case 0: src = s0; h = d0; cols4 = cs0; dstride = ds0; doff = off0; total4 = t0; break;
        case 1: src = s1; h = d1; cols4 = cs1; dstride = ds1; doff = off1; total4 = t1; break;
        case 2: src = s2; h = d2; cols4 = cs2; dstride = ds2; doff = off2; total4 = t2; break;
        default: src = s3; h = d3; cols4 = cs3; dstride = ds3; doff = off3; total4 = t3; break;
    }
    int idx = blockIdx.x * 256 + threadIdx.x;
    if (idx >= total4) return;
    int r = idx / cols4;
    int c4 = idx - r * cols4;
    float4 v = ((const float4*)src)[idx];
    size_t d = (size_t)r * dstride + doff + c4 * 4;
    *(__half2*)&h[d]     = __floats2half2_rn(v.x, v.y);
    *(__half2*)&h[d + 2] = __floats2half2_rn(v.z, v.w);
}

// ============================================================
// Kernel 3: fp16 single-pass GEMM (HMMA), optional fp16 output.
//   CTA 128x128, BK=64, 3-stage cp.async ring, XOR-swizzled smem.
// ============================================================
#define GBM 128
#define GBN 128
#define TILE_SB  16384
#define STAGE_SB 32768
#define NSTAGE   3
#define GEMM_SMEM (NSTAGE * STAGE_SB)

__global__ __launch_bounds__(256, 2) void gemm_f16(
    const __half* __restrict__ A0, const __half* __restrict__ B0,
    const float* __restrict__ bias0a, void* __restrict__ C0,
    const __half* __restrict__ A1, const __half* __restrict__ B1,
    const float* __restrict__ bias1a, void* __restrict__ C1,
    const float* __restrict__ biasExtra,
    int Ntotal, int K, int half_out)
{
    extern __shared__ char gsm[];
    uint32_t sbase = smem_u32(gsm);

    int tid = threadIdx.x;
    int m0 = blockIdx.y * GBM;
    int n0 = blockIdx.x * GBN;
    int lane = tid & 31;
    int wid = tid >> 5;
    int warp_m = (wid >> 2) * 64;
    int warp_n = (wid & 3) * 32;

    const __half* A = (blockIdx.z == 0) ? A0 : A1;
    const __half* B = (blockIdx.z == 0) ? B0 : B1;
    const float* bias = (blockIdx.z == 0) ? bias0a : bias1a;
    void* C = (blockIdx.z == 0) ? C0 : C1;

    int nslab = K >> 6;

    int l_row = tid >> 1;
    int l_c0  = (tid & 1) * 4;
    int l_sw  = l_row & 7;
    uint32_t l_sm_base = (uint32_t)(l_row * 128);

    float acc[4][4][4];
#pragma unroll
    for (int i = 0; i < 4; i++)
#pragma unroll
        for (int j = 0; j < 4; j++)
#pragma unroll
            for (int q = 0; q < 4; q++) acc[i][j][q] = 0.f;

    uint32_t a_rb[4]; int a_rs[4];
#pragma unroll
    for (int i = 0; i < 4; i++) {
        int r = warp_m + 16 * i + (lane & 15);
        a_rb[i] = (uint32_t)(r * 128);
        a_rs[i] = r & 7;
    }
    uint32_t b_rb[2]; int b_rs[2];
#pragma unroll
    for (int j = 0; j < 2; j++) {
        int r = warp_n + 16 * j + (lane & 7) + ((lane & 16) >> 1);
        b_rb[j] = (uint32_t)(r * 128);
        b_rs[j] = r & 7;
    }
    int cA0 = (lane >> 4);
    int cB0 = ((lane >> 3) & 1);

    auto load_slab = [&](int s, int buf) {
        int ks = s << 6;
        uint32_t sa = sbase + buf * STAGE_SB + l_sm_base;
        uint32_t sb = sa + TILE_SB;
        const __half* ga = A + (size_t)(m0 + l_row) * K + ks + l_c0 * 8;
        const __half* gb = B + (size_t)(n0 + l_row) * K + ks + l_c0 * 8;
#pragma unroll
        for (int q = 0; q < 4; q++) {
            int phys = ((l_c0 + q) ^ l_sw) << 4;
            CP_ASYNC16(sa + phys, ga + q * 8);
        }
#pragma unroll
        for (int q = 0; q < 4; q++) {
            int phys = ((l_c0 + q) ^ l_sw) << 4;
            CP_ASYNC16(sb + phys, gb + q * 8);
        }
    };

    load_slab(0, 0); CP_COMMIT();
    load_slab(1, 1); CP_COMMIT();

    int buf = 0, pbuf = 2;
    for (int s = 0; s < nslab; s++) {
        CP_WAIT1();
        __syncthreads();

        if (s + 2 < nslab) load_slab(s + 2, pbuf);
        CP_COMMIT();

        uint32_t sa = sbase + buf * STAGE_SB;
        uint32_t sb = sa + TILE_SB;
#pragma unroll
        for (int kk = 0; kk < 4; kk++) {
            uint32_t a[4][4];
#pragma unroll
            for (int i = 0; i < 4; i++) {
                uint32_t ad = sa + a_rb[i] + (uint32_t)((((cA0 + 2 * kk) ^ a_rs[i])) << 4);
                LDSM_X4(a[i][0], a[i][1], a[i][2], a[i][3], ad);
            }
            uint32_t b[4][2];
#pragma unroll
            for (int j = 0; j < 2; j++) {
                uint32_t bd = sb + b_rb[j] + (uint32_t)((((cB0 + 2 * kk) ^ b_rs[j])) << 4);
                uint32_t t0, t1, t2, t3;
                LDSM_X4(t0, t1, t2, t3, bd);
                b[2 * j][0] = t0; b[2 * j][1] = t1;
                b[2 * j + 1][0] = t2; b[2 * j + 1][1] = t3;
            }
#pragma unroll
            for (int i = 0; i < 4; i++)
#pragma unroll
                for (int j = 0; j < 4; j++)
                    MMA16816(acc[i][j], a[i], b[j]);
        }

        buf = (buf == 2) ? 0 : buf + 1;
        pbuf = (pbuf == 2) ? 0 : pbuf + 1;
    }

    // ---- epilogue ----
#pragma unroll
    for (int i = 0; i < 4; i++) {
        int r0 = m0 + warp_m + 16 * i + (lane >> 2);
#pragma unroll
        for (int j = 0; j < 4; j++) {
            int col = n0 + warp_n + 8 * j + (lane & 3) * 2;
            float b0v = bias[col], b1v = bias[col + 1];
            if (biasExtra) { b0v += biasExtra[col]; b1v += biasExtra[col + 1]; }
            float o00 = acc[i][j][0] + b0v, o01 = acc[i][j][1] + b1v;
            float o10 = acc[i][j][2] + b0v, o11 = acc[i][j][3] + b1v;
            if (half_out) {
                __half* Ch = (__half*)C;
                *(__half2*)(Ch + (size_t)r0 * Ntotal + col)       = __floats2half2_rn(o00, o01);
                *(__half2*)(Ch + (size_t)(r0 + 8) * Ntotal + col) = __floats2half2_rn(o10, o11);
            } else {
                float* Cf = (float*)C;
                float2 v0; v0.x = o00; v0.y = o01;
                float2 v1; v1.x = o10; v1.y = o11;
                *(float2*)(Cf + (size_t)r0 * Ntotal + col)       = v0;
                *(float2*)(Cf + (size_t)(r0 + 8) * Ntotal + col) = v1;
            }
        }
    }
}

// ============================================================
// Kernel 4: tensor-core flash, 128-q tiles, 3-stage KV ring,
//   ONE syncthreads per tile, exp2-domain softmax, global-first order.
//   Grid (NQT2, NHEAD, 4); z<2: GLOBAL (b=z), z>=2: LOCAL (b=z-2).
// ============================================================
#define FS3_Q     0
#define FS3_KV(i) (16384 + (i) * 16384)          // K at +0 (8KB), V at +8192
#define FS3_TOTAL 65536

__global__ __launch_bounds__(256) void flash_tc_kernel(
    const __half* __restrict__ qkvl, const __half* __restrict__ qkvg,
    __half* __restrict__ ao)
{
    extern __shared__ char fs[];
    uint32_t sbase = smem_u32(fs);
    uint32_t sQ = sbase + FS3_Q;

    int qt = blockIdx.x;
    int h  = blockIdx.y;
    int is_global = (blockIdx.z < 2) ? 1 : 0;
    int b  = blockIdx.z & 1;
    int q0 = qt * 128;

    const __half* qkv = is_global ? qkvg : qkvl;
    const __half* base = qkv + (size_t)b * SLEN * QKVD;
    const __half* baseQ = base + h * DHEAD;
    const __half* baseK = base + DMODEL + h * DHEAD;
    const __half* baseV = base + 2 * DMODEL + h * DHEAD;

    int tid = threadIdx.x;
    int lane = tid & 31;
    int w = tid >> 5;
    int halfc = w >> 2;

    // ---- K/V loader geometry (64 rows x 8 chunks; 2 chunks/thread each) ----
    int k_row = tid >> 2;
    int k_c0  = (tid & 3) * 2;
    int k_sw  = k_row & 7;
    uint32_t k_off = (uint32_t)(k_row * 128);

    int kt_lo, kt_hi, wlo, whi;
    if (is_global) {
        kt_lo = 0; kt_hi = NQT - 1; wlo = kt_lo; whi = kt_hi;
    } else {
        kt_lo = (2 * qt - 1 > 0) ? 2 * qt - 1 : 0;
        kt_hi = 2 * qt + 1;
        if (halfc == 0) { wlo = kt_lo; whi = 2 * qt; }
        else            { wlo = 2 * qt; whi = 2 * qt + 1; }
    }

    auto load_kv = [&](int kt, int bufi) {
        int k0r = kt * 64;
        uint32_t sK = sbase + FS3_KV(bufi);
        const __half* gk = baseK + (size_t)(k0r + k_row) * QKVD + k_c0 * 8;
        const __half* gv = baseV + (size_t)(k0r + k_row) * QKVD + k_c0 * 8;
#pragma unroll
        for (int q = 0; q < 2; q++) {
            int phys = ((k_c0 + q) ^ k_sw) << 4;
            CP_ASYNC16(sK + k_off + phys, gk + q * 8);
            CP_ASYNC16(sK + 8192 + k_off + phys, gv + q * 8);
        }
    };

    // ---- prologue: Q group first, then kv0, kv1 ----
    {
        int l_row = tid >> 1;
        int l_c0  = (tid & 1) * 4;
        int l_sw  = l_row & 7;
        uint32_t l_off = (uint32_t)(l_row * 128);
        const __half* gq = baseQ + (size_t)(q0 + l_row) * QKVD + l_c0 * 8;
#pragma unroll
        for (int q = 0; q < 4; q++)
            CP_ASYNC16(sQ + l_off + (((l_c0 + q) ^ l_sw) << 4), gq + q * 8);
        CP_COMMIT();
    }
    load_kv(kt_lo, 0); CP_COMMIT();
    int have2 = (kt_lo + 1 <= kt_hi);
    if (have2) { load_kv(kt_lo + 1, 1); CP_COMMIT(); }

    // Q ready when at most the 2 KV groups remain pending
    if (have2) CP_WAIT2(); else CP_WAIT1();
    __syncthreads();

    // ---- preload Q A-frags (scaled by QSCALE = scale*log2e) ----
    uint32_t qf[4][4];
    {
        int r = w * 16 + (lane & 15);
        uint32_t rb = (uint32_t)(r * 128);
        int rs = r & 7;
        int cA0 = lane >> 4;
        __half2 sc = __floats2half2_rn(QSCALE, QSCALE);
#pragma unroll
        for (int kk = 0; kk < 4; kk++) {
            uint32_t ad = sQ + rb + (uint32_t)(((cA0 + 2 * kk) ^ rs) << 4);
            LDSM_X4(qf[kk][0], qf[kk][1], qf[kk][2], qf[kk][3], ad);
#pragma unroll
            for (int q = 0; q < 4; q++) {
                __half2 v = *(__half2*)&qf[kk][q];
                v = __hmul2(v, sc);
                qf[kk][q] = *(uint32_t*)&v;
            }
        }
    }

    // K-frag geometry
    uint32_t kb_rb[4]; int kb_rs[4];
#pragma unroll
    for (int jj = 0; jj < 4; jj++) {
        int r = 16 * jj + (lane & 7) + ((lane & 16) >> 1);
        kb_rb[jj] = (uint32_t)(r * 128);
        kb_rs[jj] = r & 7;
    }
    int cB0 = (lane >> 3) & 1;

    float oacc[8][4];
#pragma unroll
    for (int j = 0; j < 8; j++)
#pragma unroll
        for (int q = 0; q < 4; q++) oacc[j][q] = 0.f;
    float m0f = -1e30f, m1f = -1e30f, l0f = 0.f, l1f = 0.f;

    int buf = 0;
    for (int kt = kt_lo; kt <= kt_hi; kt++) {
        // tile kt's group complete (the one group after it may still be in flight)
        if (kt < kt_hi) CP_WAIT1(); else CP_WAIT0();
        __syncthreads();   // tile kt visible; every warp finished compute(kt-1)

        // prefetch kt+2 into slot of kt-1 (safe: issued after the sync)
        if (kt + 2 <= kt_hi) { load_kv(kt + 2, (buf + 2) % 3); CP_COMMIT(); }

        if (kt >= wlo && kt <= whi) {
            uint32_t sK = sbase + FS3_KV(buf);
            uint32_t sV = sK + 8192;

            // ---- S = (Q*qscale) K^T  (log2-domain scores) ----
            float sacc[8][4];
#pragma unroll
            for (int j = 0; j < 8; j++)
#pragma unroll
                for (int q = 0; q < 4; q++) sacc[j][q] = 0.f;
#pragma unroll
            for (int kk = 0; kk < 4; kk++) {
                uint32_t bfr[8][2];
#pragma unroll
                for (int jj = 0; jj < 4; jj++) {
                    uint32_t bd = sK + kb_rb[jj] + (uint32_t)(((cB0 + 2 * kk) ^ kb_rs[jj]) << 4);
                    uint32_t t0, t1, t2, t3;
                    LDSM_X4(t0, t1, t2, t3, bd);
                    bfr[2 * jj][0] = t0; bfr[2 * jj][1] = t1;
                    bfr[2 * jj + 1][0] = t2; bfr[2 * jj + 1][1] = t3;
                }
#pragma unroll
                for (int j = 0; j < 8; j++)
                    MMA16816(sacc[j], qf[kk], bfr[j]);
            }

            // ---- online softmax in base-2 ----
            float mx0 = -1e30f, mx1 = -1e30f;
#pragma unroll
            for (int j = 0; j < 8; j++) {
                mx0 = fmaxf(mx0, fmaxf(sacc[j][0], sacc[j][1]));
                mx1 = fmaxf(mx1, fmaxf(sacc[j][2], sacc[j][3]));
            }
            mx0 = fmaxf(mx0, __shfl_xor_sync(0xffffffffu, mx0, 1));
            mx0 = fmaxf(mx0, __shfl_xor_sync(0xffffffffu, mx0, 2));
            mx1 = fmaxf(mx1, __shfl_xor_sync(0xffffffffu, mx1, 1));
            mx1 = fmaxf(mx1, __shfl_xor_sync(0xffffffffu, mx1, 2));
            float mn0 = fmaxf(m0f, mx0), mn1 = fmaxf(m1f, mx1);
            float cr0 = ex2(m0f - mn0), cr1 = ex2(m1f - mn1);
            m0f = mn0; m1f = mn1;
            float rs0 = 0.f, rs1 = 0.f;
#pragma unroll
            for (int j = 0; j < 8; j++) {
                sacc[j][0] = ex2(sacc[j][0] - mn0);
                sacc[j][1] = ex2(sacc[j][1] - mn0);
                sacc[j][2] = ex2(sacc[j][2] - mn1);
                sacc[j][3] = ex2(sacc[j][3] - mn1);
                rs0 += sacc[j][0] + sacc[j][1];
                rs1 += sacc[j][2] + sacc[j][3];
            }
            rs0 += __shfl_xor_sync(0xffffffffu, rs0, 1);
            rs0 += __shfl_xor_sync(0xffffffffu, rs0, 2);
            rs1 += __shfl_xor_sync(0xffffffffu, rs1, 1);
            rs1 += __shfl_xor_sync(0xffffffffu, rs1, 2);
            l0f = l0f * cr0 + rs0;
            l1f = l1f * cr1 + rs1;
#pragma unroll
            for (int j = 0; j < 8; j++) {
                oacc[j][0] *= cr0; oacc[j][1] *= cr0;
                oacc[j][2] *= cr1; oacc[j][3] *= cr1;
            }

            // ---- O += P V ----
#pragma unroll
            for (int t = 0; t < 4; t++) {
                uint32_t pa[4];
                pa[0] = packf2(sacc[2 * t][0], sacc[2 * t][1]);
                pa[1] = packf2(sacc[2 * t][2], sacc[2 * t][3]);
                pa[2] = packf2(sacc[2 * t + 1][0], sacc[2 * t + 1][1]);
                pa[3] = packf2(sacc[2 * t + 1][2], sacc[2 * t + 1][3]);
                int kr = 16 * t + (lane & 15);
                int dc = (lane >> 4) << 3;
#pragma unroll
                for (int g = 0; g < 4; g++) {
                    int d16 = 16 * g;
                    int chunk = (d16 + dc) >> 3;
                    uint32_t ad = sV + (uint32_t)(kr * 128) +
                                  (uint32_t)((chunk ^ (kr & 7)) << 4);
                    uint32_t r0, r1, r2, r3;
                    LDSM_X4_T(r0, r1, r2, r3, ad);
                    uint32_t vb0[2] = { r0, r1 };
                    uint32_t vb1[2] = { r2, r3 };
                    MMA16816(oacc[2 * g], pa, vb0);
                    MMA16816(oacc[2 * g + 1], pa, vb1);
                }
            }
        }
        buf = (buf == 2) ? 0 : buf + 1;
    }

    // ---- finalize ----
    float inv0 = 1.f / l0f, inv1 = 1.f / l1f;
    int colofs = is_global ? DMODEL : 0;
    int r0 = q0 + w * 16 + (lane >> 2);
    size_t db0 = (size_t)(b * SLEN + r0) * KCAT + colofs + h * DHEAD;
    size_t db1 = db0 + (size_t)8 * KCAT;
#pragma unroll
    for (int j = 0; j < 8; j++) {
        int col = 8 * j + (lane & 3) * 2;
        *(__half2*)&ao[db0 + col] = __floats2half2_rn(oacc[j][0] * inv0, oacc[j][1] * inv0);
        *(__half2*)&ao[db1 + col] = __floats2half2_rn(oacc[j][2] * inv1, oacc[j][3] * inv1);
    }
}

// ============================================================
// host launcher
// ============================================================
extern "C" void kernel_launch(void* const* d_in, const int* in_sizes, int n_in,
                              void* d_out, int out_size)
{
    const float* x      = (const float*)d_in[0];
    const float* ln_l_g = (const float*)d_in[1];
    const float* ln_l_b = (const float*)d_in[2];
    const float* Wqkv_l = (const float*)d_in[3];
    const float* bqkv_l = (const float*)d_in[4];
    const float* Wo_l   = (const float*)d_in[5];
    const float* bo_l   = (const float*)d_in[6];
    const float* ln_g_g = (const float*)d_in[7];
    const float* ln_g_b = (const float*)d_in[8];
    const float* Wqkv_g = (const float*)d_in[9];
    const float* bqkv_g = (const float*)d_in[10];
    const float* Wo_g   = (const float*)d_in[11];
    const float* bo_g   = (const float*)d_in[12];
    float* out = (float*)d_out;

    __half *xlf, *xgf, *wqlf, *wqgf, *wof, *aof, *qkv_l, *qkv_g;
    cudaGetSymbolAddress((void**)&xlf, g_xlf);
    cudaGetSymbolAddress((void**)&xgf, g_xgf);
    cudaGetSymbolAddress((void**)&qkv_l, g_qkv_l);
    cudaGetSymbolAddress((void**)&qkv_g, g_qkv_g);
    cudaGetSymbolAddress((void**)&wqlf, g_wqkvl_f);
    cudaGetSymbolAddress((void**)&wqgf, g_wqkvg_f);
    cudaGetSymbolAddress((void**)&wof, g_wo_f);
    cudaGetSymbolAddress((void**)&aof, g_aof);

    cudaFuncSetAttribute(gemm_f16, cudaFuncAttributeMaxDynamicSharedMemorySize, GEMM_SMEM);
    cudaFuncSetAttribute(flash_tc_kernel, cudaFuncAttributeMaxDynamicSharedMemorySize, FS3_TOTAL);

    // 1) dual LN -> fp16
    ln_dual_kernel<<<NROWS, 256>>>(x, ln_l_g, ln_l_b, ln_g_g, ln_g_b, xlf, xgf);

    // 2) all weight converts in one launch
    {
        int tq = QKVD * DMODEL / 4;
        int to = DMODEL * DMODEL / 4;
        dim3 g((tq + 255) / 256, 1, 4);
        convert_all<<<g, 256>>>(
            Wqkv_l, wqlf, DMODEL / 4, DMODEL, 0, tq,
            Wqkv_g, wqgf, DMODEL / 4, DMODEL, 0, tq,
            Wo_l,   wof,  DMODEL / 4, KCAT,  0, to,
            Wo_g,   wof,  DMODEL / 4, KCAT,  DMODEL, to);
    }

    // 3) batched QKV projections, fp16 output
    {
        dim3 g(QKVD / GBN, NROWS / GBM, 2);
        gemm_f16<<<g, 256, GEMM_SMEM>>>(xlf, wqlf, bqkv_l, qkv_l,
                                        xgf, wqgf, bqkv_g, qkv_g,
                                        nullptr, QKVD, DMODEL, 1);
    }

    // 4) tensor-core flash (global CTAs scheduled first)
    {
        dim3 gf(NQT2, NHEAD, BATCH * 2);
        flash_tc_kernel<<<gf, 256, FS3_TOTAL>>>(qkv_l, qkv_g, aof);
    }

    // 5) single-pass fused out-projection -> fp32 out
    {
        dim3 g(DMODEL / GBN, NROWS / GBM, 1);
        gemm_f16<<<g, 256, GEMM_SMEM>>>(aof, wof, bo_l, out,
                                        aof, wof, bo_l, out,
                                        bo_g, DMODEL, KCAT, 0);
    }
}